// round 4
// baseline (speedup 1.0000x reference)
#include <cuda_runtime.h>
#include <math.h>

// Problem constants
#define BB 2
#define TT 2048
#define HH 2048
#define NHH 16
#define HDD 128
#define MM (BB*TT)     // 4096 rows
#define FF (4*HH)      // 8192 ffn dim

// ---------------- scratch (static device globals; no allocs) ----------------
__device__ float g_h[(size_t)MM * HH];      // LN output (reused for LN1 and LN2)
__device__ float g_q[(size_t)MM * HH];
__device__ float g_k[(size_t)MM * HH];
__device__ float g_v[(size_t)MM * HH];
__device__ float g_attn[(size_t)MM * HH];
__device__ float g_act[(size_t)MM * FF];    // FFN hidden activations

__device__ __forceinline__ float gelu_tanh_f(float x) {
    float x3 = x * x * x;
    return 0.5f * x * (1.0f + tanhf(0.7978845608028654f * (x + 0.044715f * x3)));
}

// ---------------- LayerNorm: one block per row ----------------
__global__ void __launch_bounds__(256)
ln_kernel(const float* __restrict__ x, const float* __restrict__ gam,
          const float* __restrict__ bet, float* __restrict__ y)
{
    const int row = blockIdx.x;
    const int tid = threadIdx.x;
    const float* xr = x + (size_t)row * HH;
    float v[8];
    *(float4*)&v[0] = *(const float4*)(xr + tid * 8);
    *(float4*)&v[4] = *(const float4*)(xr + tid * 8 + 4);
    float s = 0.f, ss = 0.f;
    #pragma unroll
    for (int i = 0; i < 8; i++) { s += v[i]; ss = fmaf(v[i], v[i], ss); }
    #pragma unroll
    for (int off = 16; off > 0; off >>= 1) {
        s  += __shfl_xor_sync(0xffffffffu, s,  off);
        ss += __shfl_xor_sync(0xffffffffu, ss, off);
    }
    __shared__ float rs[8], rss[8], stats[2];
    const int warp = tid >> 5;
    if ((tid & 31) == 0) { rs[warp] = s; rss[warp] = ss; }
    __syncthreads();
    if (tid == 0) {
        float S = 0.f, SS = 0.f;
        #pragma unroll
        for (int w = 0; w < 8; w++) { S += rs[w]; SS += rss[w]; }
        float mean = S * (1.0f / HH);
        float var  = SS * (1.0f / HH) - mean * mean;
        stats[0] = mean;
        stats[1] = rsqrtf(var + 1e-5f);
    }
    __syncthreads();
    const float mean = stats[0], inv = stats[1];
    float g[8], b[8];
    *(float4*)&g[0] = *(const float4*)(gam + tid * 8);
    *(float4*)&g[4] = *(const float4*)(gam + tid * 8 + 4);
    *(float4*)&b[0] = *(const float4*)(bet + tid * 8);
    *(float4*)&b[4] = *(const float4*)(bet + tid * 8 + 4);
    float o[8];
    #pragma unroll
    for (int i = 0; i < 8; i++) o[i] = fmaf(g[i], (v[i] - mean) * inv, b[i]);
    float* yp = y + (size_t)row * HH + tid * 8;
    *(float4*)yp       = make_float4(o[0], o[1], o[2], o[3]);
    *(float4*)(yp + 4) = make_float4(o[4], o[5], o[6], o[7]);
}

// ---------------- GEMM: C = A[M,K] @ B[K,N], fused epilogues ----------------
// EPI 0: C = acc
// EPI 1: C = acc + res
// EPI 2: C = gelu(acc + bias[n])
// EPI 3: C = acc + bias[n] + C   (residual accumulate in-place)
template<int EPI>
__global__ void __launch_bounds__(256)
gemm_kernel(const float* __restrict__ A, const float* __restrict__ B,
            const float* __restrict__ bias, const float* __restrict__ res,
            float* __restrict__ C, int M, int N, int K)
{
    __shared__ float As[2][8][128];
    __shared__ float Bs[2][8][128];
    const int tid = threadIdx.x;
    const int m0 = blockIdx.y * 128;
    const int n0 = blockIdx.x * 128;
    const int tx = tid & 15;
    const int ty = tid >> 4;
    const int arow = tid >> 1;
    const int acol = (tid & 1) << 2;
    const int brow = tid >> 5;
    const int bcol = (tid & 31) << 2;
    const float* Ap = A + (size_t)(m0 + arow) * K + acol;
    const float* Bp = B + (size_t)brow * N + n0 + bcol;

    float acc[8][8];
    #pragma unroll
    for (int i = 0; i < 8; i++)
        #pragma unroll
        for (int j = 0; j < 8; j++) acc[i][j] = 0.f;

    float4 an = *(const float4*)Ap;
    float4 bn = *(const float4*)Bp;
    int buf = 0;
    for (int k0 = 0; k0 < K; k0 += 8) {
        As[buf][acol + 0][arow] = an.x;
        As[buf][acol + 1][arow] = an.y;
        As[buf][acol + 2][arow] = an.z;
        As[buf][acol + 3][arow] = an.w;
        *(float4*)&Bs[buf][brow][bcol] = bn;
        __syncthreads();
        if (k0 + 8 < K) {
            an = *(const float4*)(Ap + k0 + 8);
            bn = *(const float4*)(Bp + (size_t)(k0 + 8) * N);
        }
        #pragma unroll
        for (int k = 0; k < 8; k++) {
            float a[8], b[8];
            *(float4*)&a[0] = *(const float4*)&As[buf][k][ty * 8];
            *(float4*)&a[4] = *(const float4*)&As[buf][k][ty * 8 + 4];
            *(float4*)&b[0] = *(const float4*)&Bs[buf][k][tx * 8];
            *(float4*)&b[4] = *(const float4*)&Bs[buf][k][tx * 8 + 4];
            #pragma unroll
            for (int i = 0; i < 8; i++)
                #pragma unroll
                for (int j = 0; j < 8; j++)
                    acc[i][j] = fmaf(a[i], b[j], acc[i][j]);
        }
        buf ^= 1;
    }

    #pragma unroll
    for (int i = 0; i < 8; i++) {
        const int row = m0 + ty * 8 + i;
        const size_t off = (size_t)row * N + n0 + tx * 8;
        float vals[8];
        #pragma unroll
        for (int j = 0; j < 8; j++) vals[j] = acc[i][j];
        if (EPI == 1) {
            float4 r0 = *(const float4*)(res + off);
            float4 r1 = *(const float4*)(res + off + 4);
            vals[0] += r0.x; vals[1] += r0.y; vals[2] += r0.z; vals[3] += r0.w;
            vals[4] += r1.x; vals[5] += r1.y; vals[6] += r1.z; vals[7] += r1.w;
        } else if (EPI == 2) {
            #pragma unroll
            for (int j = 0; j < 8; j++)
                vals[j] = gelu_tanh_f(vals[j] + bias[n0 + tx * 8 + j]);
        } else if (EPI == 3) {
            float4 c0 = *(const float4*)(C + off);
            float4 c1 = *(const float4*)(C + off + 4);
            vals[0] += c0.x + bias[n0 + tx * 8 + 0];
            vals[1] += c0.y + bias[n0 + tx * 8 + 1];
            vals[2] += c0.z + bias[n0 + tx * 8 + 2];
            vals[3] += c0.w + bias[n0 + tx * 8 + 3];
            vals[4] += c1.x + bias[n0 + tx * 8 + 4];
            vals[5] += c1.y + bias[n0 + tx * 8 + 5];
            vals[6] += c1.z + bias[n0 + tx * 8 + 6];
            vals[7] += c1.w + bias[n0 + tx * 8 + 7];
        }
        *(float4*)(C + off)     = make_float4(vals[0], vals[1], vals[2], vals[3]);
        *(float4*)(C + off + 4) = make_float4(vals[4], vals[5], vals[6], vals[7]);
    }
}

// ---------------- Flash attention (causal), fp32 ----------------
// Grid: (T/64 q-tiles, B*NH). 256 threads. Dynamic smem 116224 B.
// Qs/Ks stored d-major [128][64] (broadcast + conflict-free S GEMM);
// P staged in smem [64][68] for the PV GEMM.
__global__ void __launch_bounds__(256)
attn_kernel(const float* __restrict__ Q, const float* __restrict__ K,
            const float* __restrict__ V, float* __restrict__ Out)
{
    extern __shared__ float sm[];
    float* Qs = sm;                    // [128][64]
    float* Ks = sm + 8192;             // [128][64]
    float* Vs = sm + 16384;            // [64][128]
    float* Ps = sm + 24576;            // [64][68]
    float* Mr = sm + 24576 + 64 * 68;  // [64]
    float* Lr = Mr + 64;               // [64]

    const int tid = threadIdx.x;
    const int tx = tid & 15;
    const int ty = tid >> 4;
    const int b = blockIdx.y >> 4;
    const int h = blockIdx.y & 15;
    const int q0 = blockIdx.x * 64;
    const size_t base = ((size_t)b * TT) * HH + (size_t)h * HDD;
    const float qscale = 0.12751744116f;   // log2(e) / sqrt(128)

    // Load Q tile, transposed to [d][r], pre-scaled
    #pragma unroll
    for (int it = 0; it < 8; it++) {
        int chunk = tid + it * 256;       // 0..2047 float4 chunks
        int r = chunk >> 5;
        int d0 = (chunk & 31) << 2;
        float4 qv = *(const float4*)(Q + base + (size_t)(q0 + r) * HH + d0);
        Qs[(d0 + 0) * 64 + r] = qv.x * qscale;
        Qs[(d0 + 1) * 64 + r] = qv.y * qscale;
        Qs[(d0 + 2) * 64 + r] = qv.z * qscale;
        Qs[(d0 + 3) * 64 + r] = qv.w * qscale;
    }
    if (tid < 64) { Mr[tid] = -1e30f; Lr[tid] = 0.f; }

    float o[4][8];
    #pragma unroll
    for (int i = 0; i < 4; i++)
        #pragma unroll
        for (int j = 0; j < 8; j++) o[i][j] = 0.f;

    const int nkt = blockIdx.x + 1;
    for (int kt = 0; kt < nkt; kt++) {
        const int k0 = kt * 64;
        __syncthreads();   // previous PV done; safe to overwrite K/V tiles (also covers Q/Mr init)
        #pragma unroll
        for (int it = 0; it < 8; it++) {
            int chunk = tid + it * 256;
            int r = chunk >> 5;
            int d0 = (chunk & 31) << 2;
            float4 kv = *(const float4*)(K + base + (size_t)(k0 + r) * HH + d0);
            Ks[(d0 + 0) * 64 + r] = kv.x;
            Ks[(d0 + 1) * 64 + r] = kv.y;
            Ks[(d0 + 2) * 64 + r] = kv.z;
            Ks[(d0 + 3) * 64 + r] = kv.w;
            float4 vv = *(const float4*)(V + base + (size_t)(k0 + r) * HH + d0);
            *(float4*)&Vs[r * 128 + d0] = vv;
        }
        __syncthreads();

        // S[4][4] per thread: rows ty*4+i, cols tx*4+j (in log2 units, pre-scaled)
        float s[4][4];
        #pragma unroll
        for (int i = 0; i < 4; i++)
            #pragma unroll
            for (int j = 0; j < 4; j++) s[i][j] = 0.f;
        for (int d = 0; d < 128; d++) {
            float qa[4], ka[4];
            *(float4*)qa = *(const float4*)&Qs[d * 64 + ty * 4];
            *(float4*)ka = *(const float4*)&Ks[d * 64 + tx * 4];
            #pragma unroll
            for (int i = 0; i < 4; i++)
                #pragma unroll
                for (int j = 0; j < 4; j++)
                    s[i][j] = fmaf(qa[i], ka[j], s[i][j]);
        }

        if (kt == nkt - 1) {   // diagonal tile: causal mask
            #pragma unroll
            for (int i = 0; i < 4; i++)
                #pragma unroll
                for (int j = 0; j < 4; j++)
                    if (tx * 4 + j > ty * 4 + i) s[i][j] = -1e30f;
        }

        // Online softmax per row (16-lane groups: lanes share ty)
        float alpha[4];
        #pragma unroll
        for (int i = 0; i < 4; i++) {
            const int r = ty * 4 + i;
            float mx = fmaxf(fmaxf(s[i][0], s[i][1]), fmaxf(s[i][2], s[i][3]));
            #pragma unroll
            for (int off = 1; off < 16; off <<= 1)
                mx = fmaxf(mx, __shfl_xor_sync(0xffffffffu, mx, off));
            const float mold = Mr[r];
            const float mnew = fmaxf(mold, mx);
            float sum = 0.f;
            #pragma unroll
            for (int j = 0; j < 4; j++) {
                float p = exp2f(s[i][j] - mnew);
                s[i][j] = p;
                sum += p;
            }
            #pragma unroll
            for (int off = 1; off < 16; off <<= 1)
                sum += __shfl_xor_sync(0xffffffffu, sum, off);
            alpha[i] = exp2f(mold - mnew);
            if (tx == 0) { Mr[r] = mnew; Lr[r] = fmaf(alpha[i], Lr[r], sum); }
            *(float4*)&Ps[r * 68 + tx * 4] = make_float4(s[i][0], s[i][1], s[i][2], s[i][3]);
        }
        __syncthreads();

        // Rescale O, then O += P @ V
        #pragma unroll
        for (int i = 0; i < 4; i++)
            #pragma unroll
            for (int j = 0; j < 8; j++) o[i][j] *= alpha[i];

        for (int k = 0; k < 64; k += 4) {
            float pr[4][4];
            *(float4*)pr[0] = *(const float4*)&Ps[(ty * 4 + 0) * 68 + k];
            *(float4*)pr[1] = *(const float4*)&Ps[(ty * 4 + 1) * 68 + k];
            *(float4*)pr[2] = *(const float4*)&Ps[(ty * 4 + 2) * 68 + k];
            *(float4*)pr[3] = *(const float4*)&Ps[(ty * 4 + 3) * 68 + k];
            #pragma unroll
            for (int kk = 0; kk < 4; kk++) {
                float va[8];
                *(float4*)&va[0] = *(const float4*)&Vs[(k + kk) * 128 + tx * 8];
                *(float4*)&va[4] = *(const float4*)&Vs[(k + kk) * 128 + tx * 8 + 4];
                #pragma unroll
                for (int i = 0; i < 4; i++)
                    #pragma unroll
                    for (int j = 0; j < 8; j++)
                        o[i][j] = fmaf(pr[i][kk], va[j], o[i][j]);
            }
        }
    }

    // Normalize and write
    #pragma unroll
    for (int i = 0; i < 4; i++) {
        const int r = ty * 4 + i;
        const float inv = 1.0f / Lr[r];
        float* op = Out + base + (size_t)(q0 + r) * HH + tx * 8;
        *(float4*)op       = make_float4(o[i][0] * inv, o[i][1] * inv, o[i][2] * inv, o[i][3] * inv);
        *(float4*)(op + 4) = make_float4(o[i][4] * inv, o[i][5] * inv, o[i][6] * inv, o[i][7] * inv);
    }
}

// ---------------- host launcher ----------------
extern "C" void kernel_launch(void* const* d_in, const int* in_sizes, int n_in,
                              void* d_out, int out_size)
{
    const float* x    = (const float*)d_in[0];
    const float* wq   = (const float*)d_in[1];
    const float* wk   = (const float*)d_in[2];
    const float* wv   = (const float*)d_in[3];
    const float* wo   = (const float*)d_in[4];
    const float* ln1s = (const float*)d_in[5];
    const float* ln1b = (const float*)d_in[6];
    const float* ln2s = (const float*)d_in[7];
    const float* ln2b = (const float*)d_in[8];
    const float* w1   = (const float*)d_in[9];
    const float* b1   = (const float*)d_in[10];
    const float* w2   = (const float*)d_in[11];
    const float* b2   = (const float*)d_in[12];
    float* out = (float*)d_out;

    float *h, *q, *k, *v, *attn, *act;
    cudaGetSymbolAddress((void**)&h,    g_h);
    cudaGetSymbolAddress((void**)&q,    g_q);
    cudaGetSymbolAddress((void**)&k,    g_k);
    cudaGetSymbolAddress((void**)&v,    g_v);
    cudaGetSymbolAddress((void**)&attn, g_attn);
    cudaGetSymbolAddress((void**)&act,  g_act);

    const int M = MM, H = HH, F = FF;
    const dim3 gH(H / 128, M / 128);

    // 1. LN1
    ln_kernel<<<M, 256>>>(x, ln1s, ln1b, h);
    // 2-4. QKV projections
    gemm_kernel<0><<<gH, 256>>>(h, wq, nullptr, nullptr, q, M, H, H);
    gemm_kernel<0><<<gH, 256>>>(h, wk, nullptr, nullptr, k, M, H, H);
    gemm_kernel<0><<<gH, 256>>>(h, wv, nullptr, nullptr, v, M, H, H);
    // 5. causal flash attention
    const int smsize = (8192 * 3 + 64 * 68 + 128) * 4;  // 116224 B
    cudaFuncSetAttribute(attn_kernel, cudaFuncAttributeMaxDynamicSharedMemorySize, smsize);
    attn_kernel<<<dim3(TT / 64, BB * NHH), 256, smsize>>>(q, k, v, attn);
    // 6. out = x + attn @ wo
    gemm_kernel<1><<<gH, 256>>>(attn, wo, nullptr, x, out, M, H, H);
    // 7. LN2
    ln_kernel<<<M, 256>>>(out, ln2s, ln2b, h);
    // 8. act = gelu(h @ w1 + b1)
    gemm_kernel<2><<<dim3(F / 128, M / 128), 256>>>(h, w1, b1, nullptr, act, M, F, H);
    // 9. out += act @ w2 + b2
    gemm_kernel<3><<<gH, 256>>>(act, w2, b2, nullptr, out, M, H, F);
}

// round 6
// speedup vs baseline: 1.7476x; 1.7476x over previous
#include <cuda_runtime.h>
#include <math.h>

// Problem constants
#define BB 2
#define TT 2048
#define HH 2048
#define NHH 16
#define HDD 128
#define MM (BB*TT)     // 4096 rows
#define FF (4*HH)      // 8192 ffn dim

// ---------------- scratch (static device globals; no allocs) ----------------
__device__ float g_h[(size_t)MM * HH];      // LN output (reused for LN1 and LN2)
__device__ float g_q[(size_t)MM * HH];
__device__ float g_k[(size_t)MM * HH];
__device__ float g_v[(size_t)MM * HH];
__device__ float g_attn[(size_t)MM * HH];
__device__ float g_act[(size_t)MM * FF];    // FFN hidden activations

__device__ __forceinline__ float gelu_tanh_f(float x) {
    float x3 = x * x * x;
    return 0.5f * x * (1.0f + tanhf(0.7978845608028654f * (x + 0.044715f * x3)));
}

__device__ __forceinline__ unsigned f2tf(float x) {
    unsigned u;
    asm("cvt.rna.tf32.f32 %0, %1;" : "=r"(u) : "f"(x));
    return u;
}

__device__ __forceinline__ void mma_tf32(float d[4], const unsigned a[4], const unsigned b[2]) {
    asm volatile(
        "mma.sync.aligned.m16n8k8.row.col.f32.tf32.tf32.f32 "
        "{%0,%1,%2,%3}, {%4,%5,%6,%7}, {%8,%9}, {%0,%1,%2,%3};\n"
        : "+f"(d[0]), "+f"(d[1]), "+f"(d[2]), "+f"(d[3])
        : "r"(a[0]), "r"(a[1]), "r"(a[2]), "r"(a[3]), "r"(b[0]), "r"(b[1]));
}

// ---------------- LayerNorm: one block per row ----------------
__global__ void __launch_bounds__(256)
ln_kernel(const float* __restrict__ x, const float* __restrict__ gam,
          const float* __restrict__ bet, float* __restrict__ y)
{
    const int row = blockIdx.x;
    const int tid = threadIdx.x;
    const float* xr = x + (size_t)row * HH;
    float v[8];
    *(float4*)&v[0] = *(const float4*)(xr + tid * 8);
    *(float4*)&v[4] = *(const float4*)(xr + tid * 8 + 4);
    float s = 0.f, ss = 0.f;
    #pragma unroll
    for (int i = 0; i < 8; i++) { s += v[i]; ss = fmaf(v[i], v[i], ss); }
    #pragma unroll
    for (int off = 16; off > 0; off >>= 1) {
        s  += __shfl_xor_sync(0xffffffffu, s,  off);
        ss += __shfl_xor_sync(0xffffffffu, ss, off);
    }
    __shared__ float rs[8], rss[8], stats[2];
    const int warp = tid >> 5;
    if ((tid & 31) == 0) { rs[warp] = s; rss[warp] = ss; }
    __syncthreads();
    if (tid == 0) {
        float S = 0.f, SS = 0.f;
        #pragma unroll
        for (int w = 0; w < 8; w++) { S += rs[w]; SS += rss[w]; }
        float mean = S * (1.0f / HH);
        float var  = SS * (1.0f / HH) - mean * mean;
        stats[0] = mean;
        stats[1] = rsqrtf(var + 1e-5f);
    }
    __syncthreads();
    const float mean = stats[0], inv = stats[1];
    float g[8], b[8];
    *(float4*)&g[0] = *(const float4*)(gam + tid * 8);
    *(float4*)&g[4] = *(const float4*)(gam + tid * 8 + 4);
    *(float4*)&b[0] = *(const float4*)(bet + tid * 8);
    *(float4*)&b[4] = *(const float4*)(bet + tid * 8 + 4);
    float o[8];
    #pragma unroll
    for (int i = 0; i < 8; i++) o[i] = fmaf(g[i], (v[i] - mean) * inv, b[i]);
    float* yp = y + (size_t)row * HH + tid * 8;
    *(float4*)yp       = make_float4(o[0], o[1], o[2], o[3]);
    *(float4*)(yp + 4) = make_float4(o[4], o[5], o[6], o[7]);
}

// ---------------- TF32 tensor-core GEMM: C = A[M,K] @ B[K,N] ----------------
// 128x128 block tile, BK=16, 8 warps (4 along M x 2 along N), warp tile 32x64.
// mma.sync m16n8k8: per warp 2 m-frags x 8 n-frags. smem k-major, stride 136
// (== 8 mod 32) -> conflict-free fragment loads AND scatter stores.
// EPI 0: C = acc
// EPI 1: C = acc + res
// EPI 2: C = gelu(acc + bias[n])
// EPI 3: C = acc + bias[n] + C   (residual accumulate in-place)
template<int EPI>
__global__ void __launch_bounds__(256)
gemm_tc(const float* __restrict__ A, const float* __restrict__ B,
        const float* __restrict__ bias, const float* __restrict__ res,
        float* __restrict__ C, int M, int N, int K)
{
    __shared__ unsigned As[2][16][136];   // [k][m]
    __shared__ unsigned Bs[2][16][136];   // [k][n]

    const int tid  = threadIdx.x;
    const int lane = tid & 31;
    const int warp = tid >> 5;
    const int l4 = lane & 3;
    const int l2 = lane >> 2;
    const int wm = (warp & 3) * 32;
    const int wn = (warp >> 2) * 64;
    const int m0 = blockIdx.y * 128;
    const int n0 = blockIdx.x * 128;

    // A gmem mapping: each thread owns one row (ar) and 2 k-chunks of 4
    const int ar  = tid & 127;
    const int akq = tid >> 7;             // 0 or 1; chunk i adds 2
    // B gmem mapping: each thread owns 2 (k, 16B-of-n) chunks
    const int bk0 = tid >> 5;             // 0..7; chunk i adds 8
    const int bn4 = (tid & 31) * 4;

    const float* Arow = A + (size_t)(m0 + ar) * K;

    float acc[2][8][4];
    #pragma unroll
    for (int mi = 0; mi < 2; mi++)
        #pragma unroll
        for (int ni = 0; ni < 8; ni++)
            #pragma unroll
            for (int r = 0; r < 4; r++) acc[mi][ni][r] = 0.f;

    float4 pa[2], pb[2];
    #pragma unroll
    for (int i = 0; i < 2; i++) {
        pa[i] = *(const float4*)(Arow + 4 * (akq + 2 * i));
        pb[i] = *(const float4*)(B + (size_t)(bk0 + 8 * i) * N + n0 + bn4);
    }
    // store tile 0 into buf 0
    #pragma unroll
    for (int i = 0; i < 2; i++) {
        const int kp = 4 * (akq + 2 * i);
        As[0][kp + 0][ar] = f2tf(pa[i].x);
        As[0][kp + 1][ar] = f2tf(pa[i].y);
        As[0][kp + 2][ar] = f2tf(pa[i].z);
        As[0][kp + 3][ar] = f2tf(pa[i].w);
        uint4 t;
        t.x = f2tf(pb[i].x); t.y = f2tf(pb[i].y);
        t.z = f2tf(pb[i].z); t.w = f2tf(pb[i].w);
        *(uint4*)&Bs[0][bk0 + 8 * i][bn4] = t;
    }

    int buf = 0;
    for (int k0 = 0; k0 < K; k0 += 16) {
        __syncthreads();
        const bool more = (k0 + 16) < K;
        if (more) {
            #pragma unroll
            for (int i = 0; i < 2; i++) {
                pa[i] = *(const float4*)(Arow + k0 + 16 + 4 * (akq + 2 * i));
                pb[i] = *(const float4*)(B + (size_t)(k0 + 16 + bk0 + 8 * i) * N + n0 + bn4);
            }
        }

        #pragma unroll
        for (int kb = 0; kb < 16; kb += 8) {
            unsigned af[2][4];
            #pragma unroll
            for (int mi = 0; mi < 2; mi++) {
                const int m = wm + mi * 16 + l2;
                af[mi][0] = As[buf][kb + l4    ][m];
                af[mi][1] = As[buf][kb + l4    ][m + 8];
                af[mi][2] = As[buf][kb + l4 + 4][m];
                af[mi][3] = As[buf][kb + l4 + 4][m + 8];
            }
            unsigned bf[8][2];
            #pragma unroll
            for (int ni = 0; ni < 8; ni++) {
                const int n = wn + ni * 8 + l2;
                bf[ni][0] = Bs[buf][kb + l4    ][n];
                bf[ni][1] = Bs[buf][kb + l4 + 4][n];
            }
            #pragma unroll
            for (int mi = 0; mi < 2; mi++)
                #pragma unroll
                for (int ni = 0; ni < 8; ni++)
                    mma_tf32(acc[mi][ni], af[mi], bf[ni]);
        }

        if (more) {
            const int nb = buf ^ 1;
            #pragma unroll
            for (int i = 0; i < 2; i++) {
                const int kp = 4 * (akq + 2 * i);
                As[nb][kp + 0][ar] = f2tf(pa[i].x);
                As[nb][kp + 1][ar] = f2tf(pa[i].y);
                As[nb][kp + 2][ar] = f2tf(pa[i].z);
                As[nb][kp + 3][ar] = f2tf(pa[i].w);
                uint4 t;
                t.x = f2tf(pb[i].x); t.y = f2tf(pb[i].y);
                t.z = f2tf(pb[i].z); t.w = f2tf(pb[i].w);
                *(uint4*)&Bs[nb][bk0 + 8 * i][bn4] = t;
            }
        }
        buf ^= 1;
    }

    // Epilogue: c-frag layout -> float2 stores (cols 2*l4, 2*l4+1)
    #pragma unroll
    for (int mi = 0; mi < 2; mi++) {
        #pragma unroll
        for (int h = 0; h < 2; h++) {
            const int row = m0 + wm + mi * 16 + h * 8 + l2;
            #pragma unroll
            for (int ni = 0; ni < 8; ni++) {
                const int col = n0 + wn + ni * 8 + l4 * 2;
                const size_t off = (size_t)row * N + col;
                float v0 = acc[mi][ni][2 * h];
                float v1 = acc[mi][ni][2 * h + 1];
                if (EPI == 1) {
                    float2 r = *(const float2*)(res + off);
                    v0 += r.x; v1 += r.y;
                } else if (EPI == 2) {
                    v0 = gelu_tanh_f(v0 + bias[col]);
                    v1 = gelu_tanh_f(v1 + bias[col + 1]);
                } else if (EPI == 3) {
                    float2 c = *(const float2*)(C + off);
                    v0 += c.x + bias[col];
                    v1 += c.y + bias[col + 1];
                }
                *(float2*)(C + off) = make_float2(v0, v1);
            }
        }
    }
}

// ---------------- Flash attention (causal), fp32 ----------------
__global__ void __launch_bounds__(256)
attn_kernel(const float* __restrict__ Q, const float* __restrict__ K,
            const float* __restrict__ V, float* __restrict__ Out)
{
    extern __shared__ float sm[];
    float* Qs = sm;                    // [128][64]
    float* Ks = sm + 8192;             // [128][64]
    float* Vs = sm + 16384;            // [64][128]
    float* Ps = sm + 24576;            // [64][68]
    float* Mr = sm + 24576 + 64 * 68;  // [64]
    float* Lr = Mr + 64;               // [64]

    const int tid = threadIdx.x;
    const int tx = tid & 15;
    const int ty = tid >> 4;
    const int b = blockIdx.y >> 4;
    const int h = blockIdx.y & 15;
    const int q0 = blockIdx.x * 64;
    const size_t base = ((size_t)b * TT) * HH + (size_t)h * HDD;
    const float qscale = 0.12751744116f;   // log2(e) / sqrt(128)

    #pragma unroll
    for (int it = 0; it < 8; it++) {
        int chunk = tid + it * 256;
        int r = chunk >> 5;
        int d0 = (chunk & 31) << 2;
        float4 qv = *(const float4*)(Q + base + (size_t)(q0 + r) * HH + d0);
        Qs[(d0 + 0) * 64 + r] = qv.x * qscale;
        Qs[(d0 + 1) * 64 + r] = qv.y * qscale;
        Qs[(d0 + 2) * 64 + r] = qv.z * qscale;
        Qs[(d0 + 3) * 64 + r] = qv.w * qscale;
    }
    if (tid < 64) { Mr[tid] = -1e30f; Lr[tid] = 0.f; }

    float o[4][8];
    #pragma unroll
    for (int i = 0; i < 4; i++)
        #pragma unroll
        for (int j = 0; j < 8; j++) o[i][j] = 0.f;

    const int nkt = blockIdx.x + 1;
    for (int kt = 0; kt < nkt; kt++) {
        const int k0 = kt * 64;
        __syncthreads();
        #pragma unroll
        for (int it = 0; it < 8; it++) {
            int chunk = tid + it * 256;
            int r = chunk >> 5;
            int d0 = (chunk & 31) << 2;
            float4 kv = *(const float4*)(K + base + (size_t)(k0 + r) * HH + d0);
            Ks[(d0 + 0) * 64 + r] = kv.x;
            Ks[(d0 + 1) * 64 + r] = kv.y;
            Ks[(d0 + 2) * 64 + r] = kv.z;
            Ks[(d0 + 3) * 64 + r] = kv.w;
            float4 vv = *(const float4*)(V + base + (size_t)(k0 + r) * HH + d0);
            *(float4*)&Vs[r * 128 + d0] = vv;
        }
        __syncthreads();

        float s[4][4];
        #pragma unroll
        for (int i = 0; i < 4; i++)
            #pragma unroll
            for (int j = 0; j < 4; j++) s[i][j] = 0.f;
        for (int d = 0; d < 128; d++) {
            float qa[4], ka[4];
            *(float4*)qa = *(const float4*)&Qs[d * 64 + ty * 4];
            *(float4*)ka = *(const float4*)&Ks[d * 64 + tx * 4];
            #pragma unroll
            for (int i = 0; i < 4; i++)
                #pragma unroll
                for (int j = 0; j < 4; j++)
                    s[i][j] = fmaf(qa[i], ka[j], s[i][j]);
        }

        if (kt == nkt - 1) {
            #pragma unroll
            for (int i = 0; i < 4; i++)
                #pragma unroll
                for (int j = 0; j < 4; j++)
                    if (tx * 4 + j > ty * 4 + i) s[i][j] = -1e30f;
        }

        float alpha[4];
        #pragma unroll
        for (int i = 0; i < 4; i++) {
            const int r = ty * 4 + i;
            float mx = fmaxf(fmaxf(s[i][0], s[i][1]), fmaxf(s[i][2], s[i][3]));
            #pragma unroll
            for (int off = 1; off < 16; off <<= 1)
                mx = fmaxf(mx, __shfl_xor_sync(0xffffffffu, mx, off));
            const float mold = Mr[r];
            const float mnew = fmaxf(mold, mx);
            float sum = 0.f;
            #pragma unroll
            for (int j = 0; j < 4; j++) {
                float p = exp2f(s[i][j] - mnew);
                s[i][j] = p;
                sum += p;
            }
            #pragma unroll
            for (int off = 1; off < 16; off <<= 1)
                sum += __shfl_xor_sync(0xffffffffu, sum, off);
            alpha[i] = exp2f(mold - mnew);
            if (tx == 0) { Mr[r] = mnew; Lr[r] = fmaf(alpha[i], Lr[r], sum); }
            *(float4*)&Ps[r * 68 + tx * 4] = make_float4(s[i][0], s[i][1], s[i][2], s[i][3]);
        }
        __syncthreads();

        #pragma unroll
        for (int i = 0; i < 4; i++)
            #pragma unroll
            for (int j = 0; j < 8; j++) o[i][j] *= alpha[i];

        for (int k = 0; k < 64; k += 4) {
            float pr[4][4];
            *(float4*)pr[0] = *(const float4*)&Ps[(ty * 4 + 0) * 68 + k];
            *(float4*)pr[1] = *(const float4*)&Ps[(ty * 4 + 1) * 68 + k];
            *(float4*)pr[2] = *(const float4*)&Ps[(ty * 4 + 2) * 68 + k];
            *(float4*)pr[3] = *(const float4*)&Ps[(ty * 4 + 3) * 68 + k];
            #pragma unroll
            for (int kk = 0; kk < 4; kk++) {
                float va[8];
                *(float4*)&va[0] = *(const float4*)&Vs[(k + kk) * 128 + tx * 8];
                *(float4*)&va[4] = *(const float4*)&Vs[(k + kk) * 128 + tx * 8 + 4];
                #pragma unroll
                for (int i = 0; i < 4; i++)
                    #pragma unroll
                    for (int j = 0; j < 8; j++)
                        o[i][j] = fmaf(pr[i][kk], va[j], o[i][j]);
            }
        }
    }

    #pragma unroll
    for (int i = 0; i < 4; i++) {
        const int r = ty * 4 + i;
        const float inv = 1.0f / Lr[r];
        float* op = Out + base + (size_t)(q0 + r) * HH + tx * 8;
        *(float4*)op       = make_float4(o[i][0] * inv, o[i][1] * inv, o[i][2] * inv, o[i][3] * inv);
        *(float4*)(op + 4) = make_float4(o[i][4] * inv, o[i][5] * inv, o[i][6] * inv, o[i][7] * inv);
    }
}

// ---------------- host launcher ----------------
extern "C" void kernel_launch(void* const* d_in, const int* in_sizes, int n_in,
                              void* d_out, int out_size)
{
    const float* x    = (const float*)d_in[0];
    const float* wq   = (const float*)d_in[1];
    const float* wk   = (const float*)d_in[2];
    const float* wv   = (const float*)d_in[3];
    const float* wo   = (const float*)d_in[4];
    const float* ln1s = (const float*)d_in[5];
    const float* ln1b = (const float*)d_in[6];
    const float* ln2s = (const float*)d_in[7];
    const float* ln2b = (const float*)d_in[8];
    const float* w1   = (const float*)d_in[9];
    const float* b1   = (const float*)d_in[10];
    const float* w2   = (const float*)d_in[11];
    const float* b2   = (const float*)d_in[12];
    float* out = (float*)d_out;

    float *h, *q, *k, *v, *attn, *act;
    cudaGetSymbolAddress((void**)&h,    g_h);
    cudaGetSymbolAddress((void**)&q,    g_q);
    cudaGetSymbolAddress((void**)&k,    g_k);
    cudaGetSymbolAddress((void**)&v,    g_v);
    cudaGetSymbolAddress((void**)&attn, g_attn);
    cudaGetSymbolAddress((void**)&act,  g_act);

    const int M = MM, H = HH, F = FF;
    const dim3 gH(H / 128, M / 128);

    // 1. LN1
    ln_kernel<<<M, 256>>>(x, ln1s, ln1b, h);
    // 2-4. QKV projections (tensor core TF32)
    gemm_tc<0><<<gH, 256>>>(h, wq, nullptr, nullptr, q, M, H, H);
    gemm_tc<0><<<gH, 256>>>(h, wk, nullptr, nullptr, k, M, H, H);
    gemm_tc<0><<<gH, 256>>>(h, wv, nullptr, nullptr, v, M, H, H);
    // 5. causal flash attention
    const int smsize = (8192 * 3 + 64 * 68 + 128) * 4;  // 116224 B
    cudaFuncSetAttribute(attn_kernel, cudaFuncAttributeMaxDynamicSharedMemorySize, smsize);
    attn_kernel<<<dim3(TT / 64, BB * NHH), 256, smsize>>>(q, k, v, attn);
    // 6. out = x + attn @ wo
    gemm_tc<1><<<gH, 256>>>(attn, wo, nullptr, x, out, M, H, H);
    // 7. LN2
    ln_kernel<<<M, 256>>>(out, ln2s, ln2b, h);
    // 8. act = gelu(h @ w1 + b1)
    gemm_tc<2><<<dim3(F / 128, M / 128), 256>>>(h, w1, b1, nullptr, act, M, F, H);
    // 9. out += act @ w2 + b2
    gemm_tc<3><<<gH, 256>>>(act, w2, b2, nullptr, out, M, H, F);
}

// round 9
// speedup vs baseline: 2.2476x; 1.2861x over previous
#include <cuda_runtime.h>
#include <math.h>

// Problem constants
#define BB 2
#define TT 2048
#define HH 2048
#define NHH 16
#define HDD 128
#define MM (BB*TT)     // 4096 rows
#define FF (4*HH)      // 8192 ffn dim

// ---------------- scratch (static device globals; no allocs) ----------------
__device__ float g_h[(size_t)MM * HH];      // LN output (reused for LN1 and LN2)
__device__ float g_q[(size_t)MM * HH];
__device__ float g_k[(size_t)MM * HH];
__device__ float g_v[(size_t)MM * HH];
__device__ float g_attn[(size_t)MM * HH];
__device__ float g_act[(size_t)MM * FF];    // FFN hidden activations

__device__ __forceinline__ float gelu_tanh_f(float x) {
    float x3 = x * x * x;
    return 0.5f * x * (1.0f + tanhf(0.7978845608028654f * (x + 0.044715f * x3)));
}

__device__ __forceinline__ unsigned f2tf(float x) {
    unsigned u;
    asm("cvt.rna.tf32.f32 %0, %1;" : "=r"(u) : "f"(x));
    return u;
}

__device__ __forceinline__ void mma_tf32(float d[4], const unsigned a[4], const unsigned b[2]) {
    asm volatile(
        "mma.sync.aligned.m16n8k8.row.col.f32.tf32.tf32.f32 "
        "{%0,%1,%2,%3}, {%4,%5,%6,%7}, {%8,%9}, {%0,%1,%2,%3};\n"
        : "+f"(d[0]), "+f"(d[1]), "+f"(d[2]), "+f"(d[3])
        : "r"(a[0]), "r"(a[1]), "r"(a[2]), "r"(a[3]), "r"(b[0]), "r"(b[1]));
}

// ---------------- LayerNorm: one block per row ----------------
__global__ void __launch_bounds__(256)
ln_kernel(const float* __restrict__ x, const float* __restrict__ gam,
          const float* __restrict__ bet, float* __restrict__ y)
{
    const int row = blockIdx.x;
    const int tid = threadIdx.x;
    const float* xr = x + (size_t)row * HH;
    float v[8];
    *(float4*)&v[0] = *(const float4*)(xr + tid * 8);
    *(float4*)&v[4] = *(const float4*)(xr + tid * 8 + 4);
    float s = 0.f, ss = 0.f;
    #pragma unroll
    for (int i = 0; i < 8; i++) { s += v[i]; ss = fmaf(v[i], v[i], ss); }
    #pragma unroll
    for (int off = 16; off > 0; off >>= 1) {
        s  += __shfl_xor_sync(0xffffffffu, s,  off);
        ss += __shfl_xor_sync(0xffffffffu, ss, off);
    }
    __shared__ float rs[8], rss[8], stats[2];
    const int warp = tid >> 5;
    if ((tid & 31) == 0) { rs[warp] = s; rss[warp] = ss; }
    __syncthreads();
    if (tid == 0) {
        float S = 0.f, SS = 0.f;
        #pragma unroll
        for (int w = 0; w < 8; w++) { S += rs[w]; SS += rss[w]; }
        float mean = S * (1.0f / HH);
        float var  = SS * (1.0f / HH) - mean * mean;
        stats[0] = mean;
        stats[1] = rsqrtf(var + 1e-5f);
    }
    __syncthreads();
    const float mean = stats[0], inv = stats[1];
    float g[8], b[8];
    *(float4*)&g[0] = *(const float4*)(gam + tid * 8);
    *(float4*)&g[4] = *(const float4*)(gam + tid * 8 + 4);
    *(float4*)&b[0] = *(const float4*)(bet + tid * 8);
    *(float4*)&b[4] = *(const float4*)(bet + tid * 8 + 4);
    float o[8];
    #pragma unroll
    for (int i = 0; i < 8; i++) o[i] = fmaf(g[i], (v[i] - mean) * inv, b[i]);
    float* yp = y + (size_t)row * HH + tid * 8;
    *(float4*)yp       = make_float4(o[0], o[1], o[2], o[3]);
    *(float4*)(yp + 4) = make_float4(o[4], o[5], o[6], o[7]);
}

// ---------------- TF32 tensor-core GEMM: C = A[M,K] @ B[K,N] ----------------
template<int EPI>
__global__ void __launch_bounds__(256)
gemm_tc(const float* __restrict__ A, const float* __restrict__ B,
        const float* __restrict__ bias, const float* __restrict__ res,
        float* __restrict__ C, int M, int N, int K)
{
    __shared__ unsigned As[2][16][136];   // [k][m]
    __shared__ unsigned Bs[2][16][136];   // [k][n]

    const int tid  = threadIdx.x;
    const int lane = tid & 31;
    const int warp = tid >> 5;
    const int l4 = lane & 3;
    const int l2 = lane >> 2;
    const int wm = (warp & 3) * 32;
    const int wn = (warp >> 2) * 64;
    const int m0 = blockIdx.y * 128;
    const int n0 = blockIdx.x * 128;

    const int ar  = tid & 127;
    const int akq = tid >> 7;
    const int bk0 = tid >> 5;
    const int bn4 = (tid & 31) * 4;

    const float* Arow = A + (size_t)(m0 + ar) * K;

    float acc[2][8][4];
    #pragma unroll
    for (int mi = 0; mi < 2; mi++)
        #pragma unroll
        for (int ni = 0; ni < 8; ni++)
            #pragma unroll
            for (int r = 0; r < 4; r++) acc[mi][ni][r] = 0.f;

    float4 pa[2], pb[2];
    #pragma unroll
    for (int i = 0; i < 2; i++) {
        pa[i] = *(const float4*)(Arow + 4 * (akq + 2 * i));
        pb[i] = *(const float4*)(B + (size_t)(bk0 + 8 * i) * N + n0 + bn4);
    }
    #pragma unroll
    for (int i = 0; i < 2; i++) {
        const int kp = 4 * (akq + 2 * i);
        As[0][kp + 0][ar] = f2tf(pa[i].x);
        As[0][kp + 1][ar] = f2tf(pa[i].y);
        As[0][kp + 2][ar] = f2tf(pa[i].z);
        As[0][kp + 3][ar] = f2tf(pa[i].w);
        uint4 t;
        t.x = f2tf(pb[i].x); t.y = f2tf(pb[i].y);
        t.z = f2tf(pb[i].z); t.w = f2tf(pb[i].w);
        *(uint4*)&Bs[0][bk0 + 8 * i][bn4] = t;
    }

    int buf = 0;
    for (int k0 = 0; k0 < K; k0 += 16) {
        __syncthreads();
        const bool more = (k0 + 16) < K;
        if (more) {
            #pragma unroll
            for (int i = 0; i < 2; i++) {
                pa[i] = *(const float4*)(Arow + k0 + 16 + 4 * (akq + 2 * i));
                pb[i] = *(const float4*)(B + (size_t)(k0 + 16 + bk0 + 8 * i) * N + n0 + bn4);
            }
        }

        #pragma unroll
        for (int kb = 0; kb < 16; kb += 8) {
            unsigned af[2][4];
            #pragma unroll
            for (int mi = 0; mi < 2; mi++) {
                const int m = wm + mi * 16 + l2;
                af[mi][0] = As[buf][kb + l4    ][m];
                af[mi][1] = As[buf][kb + l4    ][m + 8];
                af[mi][2] = As[buf][kb + l4 + 4][m];
                af[mi][3] = As[buf][kb + l4 + 4][m + 8];
            }
            unsigned bf[8][2];
            #pragma unroll
            for (int ni = 0; ni < 8; ni++) {
                const int n = wn + ni * 8 + l2;
                bf[ni][0] = Bs[buf][kb + l4    ][n];
                bf[ni][1] = Bs[buf][kb + l4 + 4][n];
            }
            #pragma unroll
            for (int mi = 0; mi < 2; mi++)
                #pragma unroll
                for (int ni = 0; ni < 8; ni++)
                    mma_tf32(acc[mi][ni], af[mi], bf[ni]);
        }

        if (more) {
            const int nb = buf ^ 1;
            #pragma unroll
            for (int i = 0; i < 2; i++) {
                const int kp = 4 * (akq + 2 * i);
                As[nb][kp + 0][ar] = f2tf(pa[i].x);
                As[nb][kp + 1][ar] = f2tf(pa[i].y);
                As[nb][kp + 2][ar] = f2tf(pa[i].z);
                As[nb][kp + 3][ar] = f2tf(pa[i].w);
                uint4 t;
                t.x = f2tf(pb[i].x); t.y = f2tf(pb[i].y);
                t.z = f2tf(pb[i].z); t.w = f2tf(pb[i].w);
                *(uint4*)&Bs[nb][bk0 + 8 * i][bn4] = t;
            }
        }
        buf ^= 1;
    }

    #pragma unroll
    for (int mi = 0; mi < 2; mi++) {
        #pragma unroll
        for (int h = 0; h < 2; h++) {
            const int row = m0 + wm + mi * 16 + h * 8 + l2;
            #pragma unroll
            for (int ni = 0; ni < 8; ni++) {
                const int col = n0 + wn + ni * 8 + l4 * 2;
                const size_t off = (size_t)row * N + col;
                float v0 = acc[mi][ni][2 * h];
                float v1 = acc[mi][ni][2 * h + 1];
                if (EPI == 1) {
                    float2 r = *(const float2*)(res + off);
                    v0 += r.x; v1 += r.y;
                } else if (EPI == 2) {
                    v0 = gelu_tanh_f(v0 + bias[col]);
                    v1 = gelu_tanh_f(v1 + bias[col + 1]);
                } else if (EPI == 3) {
                    float2 c = *(const float2*)(C + off);
                    v0 += c.x + bias[col];
                    v1 += c.y + bias[col + 1];
                }
                *(float2*)(C + off) = make_float2(v0, v1);
            }
        }
    }
}

// ---------------- TF32 tensor-core flash attention (causal) ----------------
// CTA: 128 q-rows x one head; 8 warps, warp w owns rows [16w, 16w+16).
// K-tiles of 64 keys. Q lives in registers as a-frags (loaded once).
// smem: Ks[64][132] (key-major), Vs[64][136], Ps[128][72] -> 105472 B.
// All fragment LDS and P stores verified bank-conflict-free.
__global__ void __launch_bounds__(256, 1)
attn_tc(const float* __restrict__ Q, const float* __restrict__ K,
        const float* __restrict__ V, float* __restrict__ Out)
{
    extern __shared__ unsigned smu[];
    unsigned* Ks = smu;            // [64][132]
    unsigned* Vs = smu + 8448;     // [64][136]
    unsigned* Ps = smu + 17152;    // [128][72]

    const int tid  = threadIdx.x;
    const int lane = tid & 31;
    const int warp = tid >> 5;
    const int l4 = lane & 3;
    const int l2 = lane >> 2;
    const int wm = warp * 16;
    const int blk = gridDim.x - 1 - blockIdx.x;    // heavy diagonal CTAs first
    const int q0 = blk * 128;
    const int b  = blockIdx.y >> 4;
    const int h  = blockIdx.y & 15;
    const size_t base = (size_t)b * TT * HH + (size_t)h * HDD;
    const float qscale = 0.12751744116f;   // log2(e) / sqrt(128)

    // Q a-frags: 16 k-steps x 4 regs, resident for the whole CTA
    unsigned qf[16][4];
    {
        const float* Qr0 = Q + base + (size_t)(q0 + wm + l2) * HH;
        const float* Qr1 = Qr0 + 8 * HH;
        #pragma unroll
        for (int ks = 0; ks < 16; ks++) {
            qf[ks][0] = f2tf(Qr0[ks * 8 + l4]     * qscale);
            qf[ks][1] = f2tf(Qr1[ks * 8 + l4]     * qscale);
            qf[ks][2] = f2tf(Qr0[ks * 8 + l4 + 4] * qscale);
            qf[ks][3] = f2tf(Qr1[ks * 8 + l4 + 4] * qscale);
        }
    }

    float o[16][4];                    // O accum: 16 n-frags over d=128
    #pragma unroll
    for (int nf = 0; nf < 16; nf++)
        #pragma unroll
        for (int r = 0; r < 4; r++) o[nf][r] = 0.f;
    float m0r = -1e30f, m1r = -1e30f;  // row stats (rows l2, l2+8 of band)
    float l0r = 0.f,    l1r = 0.f;

    const int nkt = 2 * blk + 2;
    for (int kt = 0; kt < nkt; kt++) {
        const int k0 = kt * 64;
        __syncthreads();               // prev PV done; safe to overwrite K/V
        #pragma unroll
        for (int it = 0; it < 8; it++) {
            int chunk = tid + it * 256;
            int key = chunk >> 5;
            int d0  = (chunk & 31) << 2;
            float4 kv = *(const float4*)(K + base + (size_t)(k0 + key) * HH + d0);
            uint4 tk;
            tk.x = f2tf(kv.x); tk.y = f2tf(kv.y); tk.z = f2tf(kv.z); tk.w = f2tf(kv.w);
            *(uint4*)&Ks[key * 132 + d0] = tk;
            float4 vv = *(const float4*)(V + base + (size_t)(k0 + key) * HH + d0);
            uint4 tv;
            tv.x = f2tf(vv.x); tv.y = f2tf(vv.y); tv.z = f2tf(vv.z); tv.w = f2tf(vv.w);
            *(uint4*)&Vs[key * 136 + d0] = tv;
        }
        __syncthreads();

        // ---- S = Q @ K^T : sc[8 n-frags][4] (in log2 units, pre-scaled) ----
        float sc[8][4];
        #pragma unroll
        for (int ni = 0; ni < 8; ni++)
            #pragma unroll
            for (int r = 0; r < 4; r++) sc[ni][r] = 0.f;
        #pragma unroll
        for (int ks = 0; ks < 16; ks++) {
            #pragma unroll
            for (int ni = 0; ni < 8; ni++) {
                unsigned bf[2];
                const unsigned* kp = &Ks[(ni * 8 + l2) * 132 + ks * 8 + l4];
                bf[0] = kp[0];
                bf[1] = kp[4];
                mma_tf32(sc[ni], qf[ks], bf);
            }
        }

        // ---- causal mask (only the last two k-tiles intersect the diagonal) ----
        if (kt >= 2 * blk) {
            const int row0 = q0 + wm + l2;
            const int row1 = row0 + 8;
            #pragma unroll
            for (int ni = 0; ni < 8; ni++) {
                const int col = k0 + ni * 8 + 2 * l4;
                if (col     > row0) sc[ni][0] = -1e30f;
                if (col + 1 > row0) sc[ni][1] = -1e30f;
                if (col     > row1) sc[ni][2] = -1e30f;
                if (col + 1 > row1) sc[ni][3] = -1e30f;
            }
        }

        // ---- online softmax in fragment registers ----
        float mx0 = -1e30f, mx1 = -1e30f;
        #pragma unroll
        for (int ni = 0; ni < 8; ni++) {
            mx0 = fmaxf(mx0, fmaxf(sc[ni][0], sc[ni][1]));
            mx1 = fmaxf(mx1, fmaxf(sc[ni][2], sc[ni][3]));
        }
        mx0 = fmaxf(mx0, __shfl_xor_sync(0xffffffffu, mx0, 1));
        mx0 = fmaxf(mx0, __shfl_xor_sync(0xffffffffu, mx0, 2));
        mx1 = fmaxf(mx1, __shfl_xor_sync(0xffffffffu, mx1, 1));
        mx1 = fmaxf(mx1, __shfl_xor_sync(0xffffffffu, mx1, 2));
        const float mn0 = fmaxf(m0r, mx0);
        const float mn1 = fmaxf(m1r, mx1);
        float sum0 = 0.f, sum1 = 0.f;
        #pragma unroll
        for (int ni = 0; ni < 8; ni++) {
            sc[ni][0] = exp2f(sc[ni][0] - mn0);
            sc[ni][1] = exp2f(sc[ni][1] - mn0);
            sc[ni][2] = exp2f(sc[ni][2] - mn1);
            sc[ni][3] = exp2f(sc[ni][3] - mn1);
            sum0 += sc[ni][0] + sc[ni][1];
            sum1 += sc[ni][2] + sc[ni][3];
        }
        sum0 += __shfl_xor_sync(0xffffffffu, sum0, 1);
        sum0 += __shfl_xor_sync(0xffffffffu, sum0, 2);
        sum1 += __shfl_xor_sync(0xffffffffu, sum1, 1);
        sum1 += __shfl_xor_sync(0xffffffffu, sum1, 2);
        const float a0 = exp2f(m0r - mn0);
        const float a1 = exp2f(m1r - mn1);
        m0r = mn0; m1r = mn1;
        l0r = fmaf(a0, l0r, sum0);
        l1r = fmaf(a1, l1r, sum1);

        // ---- stage P (tf32) for the PV mma ----
        {
            unsigned* p0 = &Ps[(wm + l2)     * 72 + 2 * l4];
            unsigned* p1 = &Ps[(wm + l2 + 8) * 72 + 2 * l4];
            #pragma unroll
            for (int ni = 0; ni < 8; ni++) {
                uint2 t0; t0.x = f2tf(sc[ni][0]); t0.y = f2tf(sc[ni][1]);
                *(uint2*)&p0[ni * 8] = t0;
                uint2 t1; t1.x = f2tf(sc[ni][2]); t1.y = f2tf(sc[ni][3]);
                *(uint2*)&p1[ni * 8] = t1;
            }
        }

        // rescale O accumulators
        #pragma unroll
        for (int nf = 0; nf < 16; nf++) {
            o[nf][0] *= a0; o[nf][1] *= a0;
            o[nf][2] *= a1; o[nf][3] *= a1;
        }
        __syncthreads();

        // ---- O += P @ V ----
        #pragma unroll
        for (int kv = 0; kv < 8; kv++) {
            unsigned af[4];
            const unsigned* pr0 = &Ps[(wm + l2)     * 72 + kv * 8 + l4];
            const unsigned* pr1 = &Ps[(wm + l2 + 8) * 72 + kv * 8 + l4];
            af[0] = pr0[0];
            af[1] = pr1[0];
            af[2] = pr0[4];
            af[3] = pr1[4];
            #pragma unroll
            for (int nf = 0; nf < 16; nf++) {
                unsigned bf[2];
                const unsigned* vp = &Vs[(kv * 8 + l4) * 136 + nf * 8 + l2];
                bf[0] = vp[0];
                bf[1] = vp[4 * 136];
                mma_tf32(o[nf], af, bf);
            }
        }
    }

    // ---- normalize and write ----
    const float inv0 = 1.0f / l0r;
    const float inv1 = 1.0f / l1r;
    float* O0 = Out + base + (size_t)(q0 + wm + l2) * HH;
    float* O1 = O0 + 8 * HH;
    #pragma unroll
    for (int nf = 0; nf < 16; nf++) {
        *(float2*)&O0[nf * 8 + 2 * l4] = make_float2(o[nf][0] * inv0, o[nf][1] * inv0);
        *(float2*)&O1[nf * 8 + 2 * l4] = make_float2(o[nf][2] * inv1, o[nf][3] * inv1);
    }
}

// ---------------- host launcher ----------------
extern "C" void kernel_launch(void* const* d_in, const int* in_sizes, int n_in,
                              void* d_out, int out_size)
{
    const float* x    = (const float*)d_in[0];
    const float* wq   = (const float*)d_in[1];
    const float* wk   = (const float*)d_in[2];
    const float* wv   = (const float*)d_in[3];
    const float* wo   = (const float*)d_in[4];
    const float* ln1s = (const float*)d_in[5];
    const float* ln1b = (const float*)d_in[6];
    const float* ln2s = (const float*)d_in[7];
    const float* ln2b = (const float*)d_in[8];
    const float* w1   = (const float*)d_in[9];
    const float* b1   = (const float*)d_in[10];
    const float* w2   = (const float*)d_in[11];
    const float* b2   = (const float*)d_in[12];
    float* out = (float*)d_out;

    float *h, *q, *k, *v, *attn, *act;
    cudaGetSymbolAddress((void**)&h,    g_h);
    cudaGetSymbolAddress((void**)&q,    g_q);
    cudaGetSymbolAddress((void**)&k,    g_k);
    cudaGetSymbolAddress((void**)&v,    g_v);
    cudaGetSymbolAddress((void**)&attn, g_attn);
    cudaGetSymbolAddress((void**)&act,  g_act);

    const int M = MM, H = HH, F = FF;
    const dim3 gH(H / 128, M / 128);

    // 1. LN1
    ln_kernel<<<M, 256>>>(x, ln1s, ln1b, h);
    // 2-4. QKV projections (tensor core TF32)
    gemm_tc<0><<<gH, 256>>>(h, wq, nullptr, nullptr, q, M, H, H);
    gemm_tc<0><<<gH, 256>>>(h, wk, nullptr, nullptr, k, M, H, H);
    gemm_tc<0><<<gH, 256>>>(h, wv, nullptr, nullptr, v, M, H, H);
    // 5. causal flash attention (tensor core TF32)
    const int smsize = (8448 + 8704 + 9216) * 4;   // 105472 B
    cudaFuncSetAttribute(attn_tc, cudaFuncAttributeMaxDynamicSharedMemorySize, smsize);
    attn_tc<<<dim3(TT / 128, BB * NHH), 256, smsize>>>(q, k, v, attn);
    // 6. out = x + attn @ wo
    gemm_tc<1><<<gH, 256>>>(attn, wo, nullptr, x, out, M, H, H);
    // 7. LN2
    ln_kernel<<<M, 256>>>(out, ln2s, ln2b, h);
    // 8. act = gelu(h @ w1 + b1)
    gemm_tc<2><<<dim3(F / 128, M / 128), 256>>>(h, w1, b1, nullptr, act, M, F, H);
    // 9. out += act @ w2 + b2
    gemm_tc<3><<<gH, 256>>>(act, w2, b2, nullptr, out, M, H, F);
}

// round 11
// speedup vs baseline: 3.3266x; 1.4800x over previous
#include <cuda_runtime.h>
#include <math.h>

// Problem constants
#define BB 2
#define TT 2048
#define HH 2048
#define NHH 16
#define HDD 128
#define MM (BB*TT)     // 4096 rows
#define FF (4*HH)      // 8192 ffn dim

// ---------------- scratch (static device globals; no allocs) ----------------
__device__ float g_h[(size_t)MM * HH];      // LN output (reused for LN1 and LN2)
__device__ float g_q[(size_t)MM * HH];
__device__ float g_k[(size_t)MM * HH];
__device__ float g_v[(size_t)MM * HH];
__device__ float g_attn[(size_t)MM * HH];
__device__ float g_act[(size_t)MM * FF];    // FFN hidden activations
// tf32-rounded weight copies
__device__ float g_wq[(size_t)HH * HH];
__device__ float g_wk[(size_t)HH * HH];
__device__ float g_wv[(size_t)HH * HH];
__device__ float g_wo[(size_t)HH * HH];
__device__ float g_w1[(size_t)HH * FF];
__device__ float g_w2[(size_t)FF * HH];

__device__ __forceinline__ float gelu_tanh_f(float x) {
    float x3 = x * x * x;
    return 0.5f * x * (1.0f + tanhf(0.7978845608028654f * (x + 0.044715f * x3)));
}

__device__ __forceinline__ unsigned f2tf(float x) {
    unsigned u;
    asm("cvt.rna.tf32.f32 %0, %1;" : "=r"(u) : "f"(x));
    return u;
}
__device__ __forceinline__ float roundtf(float x) { return __uint_as_float(f2tf(x)); }

__device__ __forceinline__ void mma_tf32(float d[4], const unsigned a[4], const unsigned b[2]) {
    asm volatile(
        "mma.sync.aligned.m16n8k8.row.col.f32.tf32.tf32.f32 "
        "{%0,%1,%2,%3}, {%4,%5,%6,%7}, {%8,%9}, {%0,%1,%2,%3};\n"
        : "+f"(d[0]), "+f"(d[1]), "+f"(d[2]), "+f"(d[3])
        : "r"(a[0]), "r"(a[1]), "r"(a[2]), "r"(a[3]), "r"(b[0]), "r"(b[1]));
}

__device__ __forceinline__ void cp16(float* smem_dst, const float* gmem_src) {
    unsigned s = (unsigned)__cvta_generic_to_shared(smem_dst);
    asm volatile("cp.async.cg.shared.global [%0], [%1], 16;\n" :: "r"(s), "l"(gmem_src));
}

// ---------------- tf32 pre-rounding of weights ----------------
__global__ void __launch_bounds__(256)
round_tf32_kernel(const float4* __restrict__ in, float4* __restrict__ out, int n4)
{
    int i = blockIdx.x * 256 + threadIdx.x;
    if (i < n4) {
        float4 v = in[i];
        float4 r;
        r.x = roundtf(v.x); r.y = roundtf(v.y);
        r.z = roundtf(v.z); r.w = roundtf(v.w);
        out[i] = r;
    }
}

// ---------------- LayerNorm: one block per row (tf32-rounded output) --------
__global__ void __launch_bounds__(256)
ln_kernel(const float* __restrict__ x, const float* __restrict__ gam,
          const float* __restrict__ bet, float* __restrict__ y)
{
    const int row = blockIdx.x;
    const int tid = threadIdx.x;
    const float* xr = x + (size_t)row * HH;
    float v[8];
    *(float4*)&v[0] = *(const float4*)(xr + tid * 8);
    *(float4*)&v[4] = *(const float4*)(xr + tid * 8 + 4);
    float s = 0.f, ss = 0.f;
    #pragma unroll
    for (int i = 0; i < 8; i++) { s += v[i]; ss = fmaf(v[i], v[i], ss); }
    #pragma unroll
    for (int off = 16; off > 0; off >>= 1) {
        s  += __shfl_xor_sync(0xffffffffu, s,  off);
        ss += __shfl_xor_sync(0xffffffffu, ss, off);
    }
    __shared__ float rs[8], rss[8], stats[2];
    const int warp = tid >> 5;
    if ((tid & 31) == 0) { rs[warp] = s; rss[warp] = ss; }
    __syncthreads();
    if (tid == 0) {
        float S = 0.f, SS = 0.f;
        #pragma unroll
        for (int w = 0; w < 8; w++) { S += rs[w]; SS += rss[w]; }
        float mean = S * (1.0f / HH);
        float var  = SS * (1.0f / HH) - mean * mean;
        stats[0] = mean;
        stats[1] = rsqrtf(var + 1e-5f);
    }
    __syncthreads();
    const float mean = stats[0], inv = stats[1];
    float g[8], b[8];
    *(float4*)&g[0] = *(const float4*)(gam + tid * 8);
    *(float4*)&g[4] = *(const float4*)(gam + tid * 8 + 4);
    *(float4*)&b[0] = *(const float4*)(bet + tid * 8);
    *(float4*)&b[4] = *(const float4*)(bet + tid * 8 + 4);
    float o[8];
    #pragma unroll
    for (int i = 0; i < 8; i++) o[i] = roundtf(fmaf(g[i], (v[i] - mean) * inv, b[i]));
    float* yp = y + (size_t)row * HH + tid * 8;
    *(float4*)yp       = make_float4(o[0], o[1], o[2], o[3]);
    *(float4*)(yp + 4) = make_float4(o[4], o[5], o[6], o[7]);
}

// ---------------- TF32 GEMM, 4-stage cp.async pipeline ----------------------
// C = A[M,K] @ B[K,N]. 128x128 tile, BK=16, 8 warps (4x2), warp tile 32x64.
// A and B must be tf32-pre-rounded (low mantissa bits zero) -> mma truncation
// is lossless. smem: A [128][20] per stage (pad: banks 20m+k distinct),
// B [16][136] per stage. 4 stages = 75776 B dynamic smem.
// EPI 0: C = acc           EPI 1: C = acc + res
// EPI 2: C = tf32(gelu(acc + bias[n]))   EPI 3: C = acc + bias[n] + C
template<int EPI>
__global__ void __launch_bounds__(256, 2)
gemm_tc(const float* __restrict__ A, const float* __restrict__ B,
        const float* __restrict__ bias, const float* __restrict__ res,
        float* __restrict__ C, int M, int N, int K)
{
    extern __shared__ float smem[];
    float* sA = smem;                 // 4 stages x 128*20
    float* sB = smem + 4 * 2560;      // 4 stages x 16*136

    const int tid  = threadIdx.x;
    const int lane = tid & 31;
    const int warp = tid >> 5;
    const int l4 = lane & 3;
    const int l2 = lane >> 2;
    const int wm = (warp & 3) * 32;
    const int wn = (warp >> 2) * 64;
    const int m0 = blockIdx.y * 128;
    const int n0 = blockIdx.x * 128;

    // copy mappings (2 x 16B per thread for A and for B, per stage)
    const int am  = tid >> 2;          // A row for chunk 0 (chunk1: +64)
    const int akq = (tid & 3) * 4;     // A k offset
    const int bk  = tid >> 5;          // B k row for chunk 0 (chunk1: +8)
    const int bnq = (tid & 31) * 4;    // B n offset

    float acc[2][8][4];
    #pragma unroll
    for (int mi = 0; mi < 2; mi++)
        #pragma unroll
        for (int ni = 0; ni < 8; ni++)
            #pragma unroll
            for (int r = 0; r < 4; r++) acc[mi][ni][r] = 0.f;

    const int nt = K >> 4;

    auto issue = [&](int stage, int kt) {
        const int k0 = kt << 4;
        float* a_s = sA + stage * 2560;
        float* b_s = sB + stage * 2176;
        cp16(a_s + am * 20 + akq,        A + (size_t)(m0 + am) * K + k0 + akq);
        cp16(a_s + (am + 64) * 20 + akq, A + (size_t)(m0 + am + 64) * K + k0 + akq);
        cp16(b_s + bk * 136 + bnq,       B + (size_t)(k0 + bk) * N + n0 + bnq);
        cp16(b_s + (bk + 8) * 136 + bnq, B + (size_t)(k0 + bk + 8) * N + n0 + bnq);
    };

    #pragma unroll
    for (int s = 0; s < 3; s++) {
        issue(s, s);
        asm volatile("cp.async.commit_group;\n");
    }

    for (int it = 0; it < nt; ++it) {
        asm volatile("cp.async.wait_group 2;\n");
        __syncthreads();
        const int pf = it + 3;
        if (pf < nt) issue(pf & 3, pf);
        asm volatile("cp.async.commit_group;\n");

        const float* As_ = sA + (it & 3) * 2560;
        const float* Bs_ = sB + (it & 3) * 2176;
        #pragma unroll
        for (int kb = 0; kb < 16; kb += 8) {
            unsigned af[2][4];
            #pragma unroll
            for (int mi = 0; mi < 2; mi++) {
                const float* ap = As_ + (wm + mi * 16 + l2) * 20 + kb + l4;
                af[mi][0] = __float_as_uint(ap[0]);
                af[mi][1] = __float_as_uint(ap[160]);      // +8 rows
                af[mi][2] = __float_as_uint(ap[4]);        // +4 k
                af[mi][3] = __float_as_uint(ap[164]);
            }
            unsigned bf[8][2];
            #pragma unroll
            for (int ni = 0; ni < 8; ni++) {
                const float* bp = Bs_ + (kb + l4) * 136 + wn + ni * 8 + l2;
                bf[ni][0] = __float_as_uint(bp[0]);
                bf[ni][1] = __float_as_uint(bp[544]);      // +4 k rows
            }
            #pragma unroll
            for (int mi = 0; mi < 2; mi++)
                #pragma unroll
                for (int ni = 0; ni < 8; ni++)
                    mma_tf32(acc[mi][ni], af[mi], bf[ni]);
        }
    }

    // Epilogue: c-frag layout -> float2 stores (cols 2*l4, 2*l4+1)
    #pragma unroll
    for (int mi = 0; mi < 2; mi++) {
        #pragma unroll
        for (int h = 0; h < 2; h++) {
            const int row = m0 + wm + mi * 16 + h * 8 + l2;
            #pragma unroll
            for (int ni = 0; ni < 8; ni++) {
                const int col = n0 + wn + ni * 8 + l4 * 2;
                const size_t off = (size_t)row * N + col;
                float v0 = acc[mi][ni][2 * h];
                float v1 = acc[mi][ni][2 * h + 1];
                if (EPI == 1) {
                    float2 r = *(const float2*)(res + off);
                    v0 += r.x; v1 += r.y;
                } else if (EPI == 2) {
                    v0 = roundtf(gelu_tanh_f(v0 + bias[col]));
                    v1 = roundtf(gelu_tanh_f(v1 + bias[col + 1]));
                } else if (EPI == 3) {
                    float2 c = *(const float2*)(C + off);
                    v0 += c.x + bias[col];
                    v1 += c.y + bias[col + 1];
                }
                *(float2*)(C + off) = make_float2(v0, v1);
            }
        }
    }
}

// ---------------- TF32 tensor-core flash attention (causal) ----------------
// CTA: 128 q-rows x one head; 8 warps, warp w owns rows [16w, 16w+16).
// K-tiles of 64 keys. Q lives in registers as a-frags (loaded once).
// smem: Ks[64][132] (key-major), Vs[64][136], Ps[128][72] -> 105472 B.
__global__ void __launch_bounds__(256, 1)
attn_tc(const float* __restrict__ Q, const float* __restrict__ K,
        const float* __restrict__ V, float* __restrict__ Out)
{
    extern __shared__ unsigned smu[];
    unsigned* Ks = smu;            // [64][132]
    unsigned* Vs = smu + 8448;     // [64][136]
    unsigned* Ps = smu + 17152;    // [128][72]

    const int tid  = threadIdx.x;
    const int lane = tid & 31;
    const int warp = tid >> 5;
    const int l4 = lane & 3;
    const int l2 = lane >> 2;
    const int wm = warp * 16;
    const int blk = gridDim.x - 1 - blockIdx.x;    // heavy diagonal CTAs first
    const int q0 = blk * 128;
    const int b  = blockIdx.y >> 4;
    const int h  = blockIdx.y & 15;
    const size_t base = (size_t)b * TT * HH + (size_t)h * HDD;
    const float qscale = 0.12751744116f;   // log2(e) / sqrt(128)

    // Q a-frags: 16 k-steps x 4 regs, resident for the whole CTA
    unsigned qf[16][4];
    {
        const float* Qr0 = Q + base + (size_t)(q0 + wm + l2) * HH;
        const float* Qr1 = Qr0 + 8 * HH;
        #pragma unroll
        for (int ks = 0; ks < 16; ks++) {
            qf[ks][0] = f2tf(Qr0[ks * 8 + l4]     * qscale);
            qf[ks][1] = f2tf(Qr1[ks * 8 + l4]     * qscale);
            qf[ks][2] = f2tf(Qr0[ks * 8 + l4 + 4] * qscale);
            qf[ks][3] = f2tf(Qr1[ks * 8 + l4 + 4] * qscale);
        }
    }

    float o[16][4];
    #pragma unroll
    for (int nf = 0; nf < 16; nf++)
        #pragma unroll
        for (int r = 0; r < 4; r++) o[nf][r] = 0.f;
    float m0r = -1e30f, m1r = -1e30f;
    float l0r = 0.f,    l1r = 0.f;

    const int nkt = 2 * blk + 2;
    for (int kt = 0; kt < nkt; kt++) {
        const int k0 = kt * 64;
        __syncthreads();
        #pragma unroll
        for (int it = 0; it < 8; it++) {
            int chunk = tid + it * 256;
            int key = chunk >> 5;
            int d0  = (chunk & 31) << 2;
            float4 kv = *(const float4*)(K + base + (size_t)(k0 + key) * HH + d0);
            uint4 tk;
            tk.x = f2tf(kv.x); tk.y = f2tf(kv.y); tk.z = f2tf(kv.z); tk.w = f2tf(kv.w);
            *(uint4*)&Ks[key * 132 + d0] = tk;
            float4 vv = *(const float4*)(V + base + (size_t)(k0 + key) * HH + d0);
            uint4 tv;
            tv.x = f2tf(vv.x); tv.y = f2tf(vv.y); tv.z = f2tf(vv.z); tv.w = f2tf(vv.w);
            *(uint4*)&Vs[key * 136 + d0] = tv;
        }
        __syncthreads();

        // ---- S = Q @ K^T ----
        float sc[8][4];
        #pragma unroll
        for (int ni = 0; ni < 8; ni++)
            #pragma unroll
            for (int r = 0; r < 4; r++) sc[ni][r] = 0.f;
        #pragma unroll
        for (int ks = 0; ks < 16; ks++) {
            #pragma unroll
            for (int ni = 0; ni < 8; ni++) {
                unsigned bf[2];
                const unsigned* kp = &Ks[(ni * 8 + l2) * 132 + ks * 8 + l4];
                bf[0] = kp[0];
                bf[1] = kp[4];
                mma_tf32(sc[ni], qf[ks], bf);
            }
        }

        // ---- causal mask ----
        if (kt >= 2 * blk) {
            const int row0 = q0 + wm + l2;
            const int row1 = row0 + 8;
            #pragma unroll
            for (int ni = 0; ni < 8; ni++) {
                const int col = k0 + ni * 8 + 2 * l4;
                if (col     > row0) sc[ni][0] = -1e30f;
                if (col + 1 > row0) sc[ni][1] = -1e30f;
                if (col     > row1) sc[ni][2] = -1e30f;
                if (col + 1 > row1) sc[ni][3] = -1e30f;
            }
        }

        // ---- online softmax in fragment registers ----
        float mx0 = -1e30f, mx1 = -1e30f;
        #pragma unroll
        for (int ni = 0; ni < 8; ni++) {
            mx0 = fmaxf(mx0, fmaxf(sc[ni][0], sc[ni][1]));
            mx1 = fmaxf(mx1, fmaxf(sc[ni][2], sc[ni][3]));
        }
        mx0 = fmaxf(mx0, __shfl_xor_sync(0xffffffffu, mx0, 1));
        mx0 = fmaxf(mx0, __shfl_xor_sync(0xffffffffu, mx0, 2));
        mx1 = fmaxf(mx1, __shfl_xor_sync(0xffffffffu, mx1, 1));
        mx1 = fmaxf(mx1, __shfl_xor_sync(0xffffffffu, mx1, 2));
        const float mn0 = fmaxf(m0r, mx0);
        const float mn1 = fmaxf(m1r, mx1);
        float sum0 = 0.f, sum1 = 0.f;
        #pragma unroll
        for (int ni = 0; ni < 8; ni++) {
            sc[ni][0] = exp2f(sc[ni][0] - mn0);
            sc[ni][1] = exp2f(sc[ni][1] - mn0);
            sc[ni][2] = exp2f(sc[ni][2] - mn1);
            sc[ni][3] = exp2f(sc[ni][3] - mn1);
            sum0 += sc[ni][0] + sc[ni][1];
            sum1 += sc[ni][2] + sc[ni][3];
        }
        sum0 += __shfl_xor_sync(0xffffffffu, sum0, 1);
        sum0 += __shfl_xor_sync(0xffffffffu, sum0, 2);
        sum1 += __shfl_xor_sync(0xffffffffu, sum1, 1);
        sum1 += __shfl_xor_sync(0xffffffffu, sum1, 2);
        const float a0 = exp2f(m0r - mn0);
        const float a1 = exp2f(m1r - mn1);
        m0r = mn0; m1r = mn1;
        l0r = fmaf(a0, l0r, sum0);
        l1r = fmaf(a1, l1r, sum1);

        // ---- stage P (tf32) ----
        {
            unsigned* p0 = &Ps[(wm + l2)     * 72 + 2 * l4];
            unsigned* p1 = &Ps[(wm + l2 + 8) * 72 + 2 * l4];
            #pragma unroll
            for (int ni = 0; ni < 8; ni++) {
                uint2 t0; t0.x = f2tf(sc[ni][0]); t0.y = f2tf(sc[ni][1]);
                *(uint2*)&p0[ni * 8] = t0;
                uint2 t1; t1.x = f2tf(sc[ni][2]); t1.y = f2tf(sc[ni][3]);
                *(uint2*)&p1[ni * 8] = t1;
            }
        }

        #pragma unroll
        for (int nf = 0; nf < 16; nf++) {
            o[nf][0] *= a0; o[nf][1] *= a0;
            o[nf][2] *= a1; o[nf][3] *= a1;
        }
        __syncthreads();

        // ---- O += P @ V ----
        #pragma unroll
        for (int kv = 0; kv < 8; kv++) {
            unsigned af[4];
            const unsigned* pr0 = &Ps[(wm + l2)     * 72 + kv * 8 + l4];
            const unsigned* pr1 = &Ps[(wm + l2 + 8) * 72 + kv * 8 + l4];
            af[0] = pr0[0];
            af[1] = pr1[0];
            af[2] = pr0[4];
            af[3] = pr1[4];
            #pragma unroll
            for (int nf = 0; nf < 16; nf++) {
                unsigned bf[2];
                const unsigned* vp = &Vs[(kv * 8 + l4) * 136 + nf * 8 + l2];
                bf[0] = vp[0];
                bf[1] = vp[4 * 136];
                mma_tf32(o[nf], af, bf);
            }
        }
    }

    // ---- normalize and write (tf32-rounded: feeds gemm<1> A via cp.async) ----
    const float inv0 = 1.0f / l0r;
    const float inv1 = 1.0f / l1r;
    float* O0 = Out + base + (size_t)(q0 + wm + l2) * HH;
    float* O1 = O0 + 8 * HH;
    #pragma unroll
    for (int nf = 0; nf < 16; nf++) {
        *(float2*)&O0[nf * 8 + 2 * l4] = make_float2(roundtf(o[nf][0] * inv0), roundtf(o[nf][1] * inv0));
        *(float2*)&O1[nf * 8 + 2 * l4] = make_float2(roundtf(o[nf][2] * inv1), roundtf(o[nf][3] * inv1));
    }
}

// ---------------- host launcher ----------------
extern "C" void kernel_launch(void* const* d_in, const int* in_sizes, int n_in,
                              void* d_out, int out_size)
{
    const float* x    = (const float*)d_in[0];
    const float* wq   = (const float*)d_in[1];
    const float* wk   = (const float*)d_in[2];
    const float* wv   = (const float*)d_in[3];
    const float* wo   = (const float*)d_in[4];
    const float* ln1s = (const float*)d_in[5];
    const float* ln1b = (const float*)d_in[6];
    const float* ln2s = (const float*)d_in[7];
    const float* ln2b = (const float*)d_in[8];
    const float* w1   = (const float*)d_in[9];
    const float* b1   = (const float*)d_in[10];
    const float* w2   = (const float*)d_in[11];
    const float* b2   = (const float*)d_in[12];
    float* out = (float*)d_out;

    float *h, *q, *k, *v, *attn, *act;
    float *cwq, *cwk, *cwv, *cwo, *cw1, *cw2;
    cudaGetSymbolAddress((void**)&h,    g_h);
    cudaGetSymbolAddress((void**)&q,    g_q);
    cudaGetSymbolAddress((void**)&k,    g_k);
    cudaGetSymbolAddress((void**)&v,    g_v);
    cudaGetSymbolAddress((void**)&attn, g_attn);
    cudaGetSymbolAddress((void**)&act,  g_act);
    cudaGetSymbolAddress((void**)&cwq,  g_wq);
    cudaGetSymbolAddress((void**)&cwk,  g_wk);
    cudaGetSymbolAddress((void**)&cwv,  g_wv);
    cudaGetSymbolAddress((void**)&cwo,  g_wo);
    cudaGetSymbolAddress((void**)&cw1,  g_w1);
    cudaGetSymbolAddress((void**)&cw2,  g_w2);

    const int M = MM, H = HH, F = FF;
    const dim3 gH(H / 128, M / 128);
    const int gsm = (4 * 2560 + 4 * 2176) * 4;     // 75776 B
    cudaFuncSetAttribute(gemm_tc<0>, cudaFuncAttributeMaxDynamicSharedMemorySize, gsm);
    cudaFuncSetAttribute(gemm_tc<1>, cudaFuncAttributeMaxDynamicSharedMemorySize, gsm);
    cudaFuncSetAttribute(gemm_tc<2>, cudaFuncAttributeMaxDynamicSharedMemorySize, gsm);
    cudaFuncSetAttribute(gemm_tc<3>, cudaFuncAttributeMaxDynamicSharedMemorySize, gsm);

    // 0. pre-round weights to tf32 (once per replay; ~80us of HBM traffic)
    {
        const int nHH = H * H / 4, nHF = H * F / 4;
        round_tf32_kernel<<<(nHH + 255) / 256, 256>>>((const float4*)wq, (float4*)cwq, nHH);
        round_tf32_kernel<<<(nHH + 255) / 256, 256>>>((const float4*)wk, (float4*)cwk, nHH);
        round_tf32_kernel<<<(nHH + 255) / 256, 256>>>((const float4*)wv, (float4*)cwv, nHH);
        round_tf32_kernel<<<(nHH + 255) / 256, 256>>>((const float4*)wo, (float4*)cwo, nHH);
        round_tf32_kernel<<<(nHF + 255) / 256, 256>>>((const float4*)w1, (float4*)cw1, nHF);
        round_tf32_kernel<<<(nHF + 255) / 256, 256>>>((const float4*)w2, (float4*)cw2, nHF);
    }

    // 1. LN1 (tf32-rounded output)
    ln_kernel<<<M, 256>>>(x, ln1s, ln1b, h);
    // 2-4. QKV projections
    gemm_tc<0><<<gH, 256, gsm>>>(h, cwq, nullptr, nullptr, q, M, H, H);
    gemm_tc<0><<<gH, 256, gsm>>>(h, cwk, nullptr, nullptr, k, M, H, H);
    gemm_tc<0><<<gH, 256, gsm>>>(h, cwv, nullptr, nullptr, v, M, H, H);
    // 5. causal flash attention
    const int smsize = (8448 + 8704 + 9216) * 4;   // 105472 B
    cudaFuncSetAttribute(attn_tc, cudaFuncAttributeMaxDynamicSharedMemorySize, smsize);
    attn_tc<<<dim3(TT / 128, BB * NHH), 256, smsize>>>(q, k, v, attn);
    // 6. out = x + attn @ wo
    gemm_tc<1><<<gH, 256, gsm>>>(attn, cwo, nullptr, x, out, M, H, H);
    // 7. LN2
    ln_kernel<<<M, 256>>>(out, ln2s, ln2b, h);
    // 8. act = gelu(h @ w1 + b1)
    gemm_tc<2><<<dim3(F / 128, M / 128), 256, gsm>>>(h, cw1, b1, nullptr, act, M, F, H);
    // 9. out += act @ w2 + b2
    gemm_tc<3><<<gH, 256, gsm>>>(act, cw2, b2, nullptr, out, M, H, F);
}

// round 13
// speedup vs baseline: 3.3647x; 1.0114x over previous
#include <cuda_runtime.h>
#include <math.h>

// Problem constants
#define BB 2
#define TT 2048
#define HH 2048
#define NHH 16
#define HDD 128
#define MM (BB*TT)     // 4096 rows
#define FF (4*HH)      // 8192 ffn dim

// ---------------- scratch (static device globals; no allocs) ----------------
__device__ float g_h[(size_t)MM * HH];      // LN output (reused for LN1 and LN2)
__device__ float g_q[(size_t)MM * HH];
__device__ float g_k[(size_t)MM * HH];
__device__ float g_v[(size_t)MM * HH];
__device__ float g_attn[(size_t)MM * HH];
__device__ float g_act[(size_t)MM * FF];    // FFN hidden activations
// tf32-rounded weight copies
__device__ float g_wq[(size_t)HH * HH];
__device__ float g_wk[(size_t)HH * HH];
__device__ float g_wv[(size_t)HH * HH];
__device__ float g_wo[(size_t)HH * HH];
__device__ float g_w1[(size_t)HH * FF];
__device__ float g_w2[(size_t)FF * HH];

__device__ __forceinline__ float gelu_tanh_f(float x) {
    float x3 = x * x * x;
    return 0.5f * x * (1.0f + tanhf(0.7978845608028654f * (x + 0.044715f * x3)));
}

__device__ __forceinline__ unsigned f2tf(float x) {
    unsigned u;
    asm("cvt.rna.tf32.f32 %0, %1;" : "=r"(u) : "f"(x));
    return u;
}
__device__ __forceinline__ float roundtf(float x) { return __uint_as_float(f2tf(x)); }

__device__ __forceinline__ void mma_tf32(float d[4], const unsigned a[4], const unsigned b[2]) {
    asm volatile(
        "mma.sync.aligned.m16n8k8.row.col.f32.tf32.tf32.f32 "
        "{%0,%1,%2,%3}, {%4,%5,%6,%7}, {%8,%9}, {%0,%1,%2,%3};\n"
        : "+f"(d[0]), "+f"(d[1]), "+f"(d[2]), "+f"(d[3])
        : "r"(a[0]), "r"(a[1]), "r"(a[2]), "r"(a[3]), "r"(b[0]), "r"(b[1]));
}

__device__ __forceinline__ void cp16(void* smem_dst, const void* gmem_src) {
    unsigned s = (unsigned)__cvta_generic_to_shared(smem_dst);
    asm volatile("cp.async.cg.shared.global [%0], [%1], 16;\n" :: "r"(s), "l"(gmem_src));
}

// ---------------- tf32 pre-rounding of weights ----------------
__global__ void __launch_bounds__(256)
round_tf32_kernel(const float4* __restrict__ in, float4* __restrict__ out, int n4)
{
    int i = blockIdx.x * 256 + threadIdx.x;
    if (i < n4) {
        float4 v = in[i];
        float4 r;
        r.x = roundtf(v.x); r.y = roundtf(v.y);
        r.z = roundtf(v.z); r.w = roundtf(v.w);
        out[i] = r;
    }
}

// ---------------- LayerNorm: one block per row (tf32-rounded output) --------
__global__ void __launch_bounds__(256)
ln_kernel(const float* __restrict__ x, const float* __restrict__ gam,
          const float* __restrict__ bet, float* __restrict__ y)
{
    const int row = blockIdx.x;
    const int tid = threadIdx.x;
    const float* xr = x + (size_t)row * HH;
    float v[8];
    *(float4*)&v[0] = *(const float4*)(xr + tid * 8);
    *(float4*)&v[4] = *(const float4*)(xr + tid * 8 + 4);
    float s = 0.f, ss = 0.f;
    #pragma unroll
    for (int i = 0; i < 8; i++) { s += v[i]; ss = fmaf(v[i], v[i], ss); }
    #pragma unroll
    for (int off = 16; off > 0; off >>= 1) {
        s  += __shfl_xor_sync(0xffffffffu, s,  off);
        ss += __shfl_xor_sync(0xffffffffu, ss, off);
    }
    __shared__ float rs[8], rss[8], stats[2];
    const int warp = tid >> 5;
    if ((tid & 31) == 0) { rs[warp] = s; rss[warp] = ss; }
    __syncthreads();
    if (tid == 0) {
        float S = 0.f, SS = 0.f;
        #pragma unroll
        for (int w = 0; w < 8; w++) { S += rs[w]; SS += rss[w]; }
        float mean = S * (1.0f / HH);
        float var  = SS * (1.0f / HH) - mean * mean;
        stats[0] = mean;
        stats[1] = rsqrtf(var + 1e-5f);
    }
    __syncthreads();
    const float mean = stats[0], inv = stats[1];
    float g[8], b[8];
    *(float4*)&g[0] = *(const float4*)(gam + tid * 8);
    *(float4*)&g[4] = *(const float4*)(gam + tid * 8 + 4);
    *(float4*)&b[0] = *(const float4*)(bet + tid * 8);
    *(float4*)&b[4] = *(const float4*)(bet + tid * 8 + 4);
    float o[8];
    #pragma unroll
    for (int i = 0; i < 8; i++) o[i] = roundtf(fmaf(g[i], (v[i] - mean) * inv, b[i]));
    float* yp = y + (size_t)row * HH + tid * 8;
    *(float4*)yp       = make_float4(o[0], o[1], o[2], o[3]);
    *(float4*)(yp + 4) = make_float4(o[4], o[5], o[6], o[7]);
}

// ---------------- TF32 GEMM, 4-stage cp.async pipeline ----------------------
// EPI 0: C = tf32(acc)     EPI 1: C = acc + res
// EPI 2: C = tf32(gelu(acc + bias[n]))   EPI 3: C = acc + bias[n] + C
template<int EPI>
__global__ void __launch_bounds__(256, 2)
gemm_tc(const float* __restrict__ A, const float* __restrict__ B,
        const float* __restrict__ bias, const float* __restrict__ res,
        float* __restrict__ C, int M, int N, int K)
{
    extern __shared__ float smem[];
    float* sA = smem;                 // 4 stages x 128*20
    float* sB = smem + 4 * 2560;      // 4 stages x 16*136

    const int tid  = threadIdx.x;
    const int lane = tid & 31;
    const int warp = tid >> 5;
    const int l4 = lane & 3;
    const int l2 = lane >> 2;
    const int wm = (warp & 3) * 32;
    const int wn = (warp >> 2) * 64;
    const int m0 = blockIdx.y * 128;
    const int n0 = blockIdx.x * 128;

    const int am  = tid >> 2;
    const int akq = (tid & 3) * 4;
    const int bk  = tid >> 5;
    const int bnq = (tid & 31) * 4;

    float acc[2][8][4];
    #pragma unroll
    for (int mi = 0; mi < 2; mi++)
        #pragma unroll
        for (int ni = 0; ni < 8; ni++)
            #pragma unroll
            for (int r = 0; r < 4; r++) acc[mi][ni][r] = 0.f;

    const int nt = K >> 4;

    auto issue = [&](int stage, int kt) {
        const int k0 = kt << 4;
        float* a_s = sA + stage * 2560;
        float* b_s = sB + stage * 2176;
        cp16(a_s + am * 20 + akq,        A + (size_t)(m0 + am) * K + k0 + akq);
        cp16(a_s + (am + 64) * 20 + akq, A + (size_t)(m0 + am + 64) * K + k0 + akq);
        cp16(b_s + bk * 136 + bnq,       B + (size_t)(k0 + bk) * N + n0 + bnq);
        cp16(b_s + (bk + 8) * 136 + bnq, B + (size_t)(k0 + bk + 8) * N + n0 + bnq);
    };

    #pragma unroll
    for (int s = 0; s < 3; s++) {
        issue(s, s);
        asm volatile("cp.async.commit_group;\n");
    }

    for (int it = 0; it < nt; ++it) {
        asm volatile("cp.async.wait_group 2;\n");
        __syncthreads();
        const int pf = it + 3;
        if (pf < nt) issue(pf & 3, pf);
        asm volatile("cp.async.commit_group;\n");

        const float* As_ = sA + (it & 3) * 2560;
        const float* Bs_ = sB + (it & 3) * 2176;
        #pragma unroll
        for (int kb = 0; kb < 16; kb += 8) {
            unsigned af[2][4];
            #pragma unroll
            for (int mi = 0; mi < 2; mi++) {
                const float* ap = As_ + (wm + mi * 16 + l2) * 20 + kb + l4;
                af[mi][0] = __float_as_uint(ap[0]);
                af[mi][1] = __float_as_uint(ap[160]);
                af[mi][2] = __float_as_uint(ap[4]);
                af[mi][3] = __float_as_uint(ap[164]);
            }
            unsigned bf[8][2];
            #pragma unroll
            for (int ni = 0; ni < 8; ni++) {
                const float* bp = Bs_ + (kb + l4) * 136 + wn + ni * 8 + l2;
                bf[ni][0] = __float_as_uint(bp[0]);
                bf[ni][1] = __float_as_uint(bp[544]);
            }
            #pragma unroll
            for (int mi = 0; mi < 2; mi++)
                #pragma unroll
                for (int ni = 0; ni < 8; ni++)
                    mma_tf32(acc[mi][ni], af[mi], bf[ni]);
        }
    }

    #pragma unroll
    for (int mi = 0; mi < 2; mi++) {
        #pragma unroll
        for (int h = 0; h < 2; h++) {
            const int row = m0 + wm + mi * 16 + h * 8 + l2;
            #pragma unroll
            for (int ni = 0; ni < 8; ni++) {
                const int col = n0 + wn + ni * 8 + l4 * 2;
                const size_t off = (size_t)row * N + col;
                float v0 = acc[mi][ni][2 * h];
                float v1 = acc[mi][ni][2 * h + 1];
                if (EPI == 0) {
                    v0 = roundtf(v0); v1 = roundtf(v1);   // QKV feed attn raw cp.async
                } else if (EPI == 1) {
                    float2 r = *(const float2*)(res + off);
                    v0 += r.x; v1 += r.y;
                } else if (EPI == 2) {
                    v0 = roundtf(gelu_tanh_f(v0 + bias[col]));
                    v1 = roundtf(gelu_tanh_f(v1 + bias[col + 1]));
                } else if (EPI == 3) {
                    float2 c = *(const float2*)(C + off);
                    v0 += c.x + bias[col];
                    v1 += c.y + bias[col + 1];
                }
                *(float2*)(C + off) = make_float2(v0, v1);
            }
        }
    }
}

// ---------------- TF32 flash attention, 2-stage cp.async K/V pipeline -------
// CTA: 128 q-rows x one head; 8 warps, warp w owns rows [16w, 16w+16).
// K/V inputs are tf32-pre-rounded by the QKV GEMM epilogue -> raw cp.async,
// mma truncation lossless. smem per stage: Ks[64][132], Vs[64][136];
// 2 stages + Ps[128][72] -> 174080 B.
__global__ void __launch_bounds__(256, 1)
attn_tc(const float* __restrict__ Q, const float* __restrict__ K,
        const float* __restrict__ V, float* __restrict__ Out)
{
    extern __shared__ unsigned smu[];
    // stage s: K at s*17152, V at s*17152 + 8448
    unsigned* Ps = smu + 34304;    // [128][72]

    const int tid  = threadIdx.x;
    const int lane = tid & 31;
    const int warp = tid >> 5;
    const int l4 = lane & 3;
    const int l2 = lane >> 2;
    const int wm = warp * 16;
    const int blk = gridDim.x - 1 - blockIdx.x;    // heavy diagonal CTAs first
    const int q0 = blk * 128;
    const int b  = blockIdx.y >> 4;
    const int h  = blockIdx.y & 15;
    const size_t base = (size_t)b * TT * HH + (size_t)h * HDD;
    const float qscale = 0.12751744116f;   // log2(e) / sqrt(128)

    const int nkt = 2 * blk + 2;

    auto issue_kv = [&](int stage, int kt) {
        unsigned* Ks = smu + stage * 17152;
        unsigned* Vs = Ks + 8448;
        const int k0 = kt * 64;
        #pragma unroll
        for (int it = 0; it < 8; it++) {
            int chunk = tid + it * 256;
            int key = chunk >> 5;
            int d0  = (chunk & 31) << 2;
            cp16(&Ks[key * 132 + d0], K + base + (size_t)(k0 + key) * HH + d0);
            cp16(&Vs[key * 136 + d0], V + base + (size_t)(k0 + key) * HH + d0);
        }
    };

    issue_kv(0, 0);
    asm volatile("cp.async.commit_group;\n");

    // Q a-frags: 16 k-steps x 4 regs, resident for the whole CTA
    unsigned qf[16][4];
    {
        const float* Qr0 = Q + base + (size_t)(q0 + wm + l2) * HH;
        const float* Qr1 = Qr0 + 8 * HH;
        #pragma unroll
        for (int ks = 0; ks < 16; ks++) {
            qf[ks][0] = f2tf(Qr0[ks * 8 + l4]     * qscale);
            qf[ks][1] = f2tf(Qr1[ks * 8 + l4]     * qscale);
            qf[ks][2] = f2tf(Qr0[ks * 8 + l4 + 4] * qscale);
            qf[ks][3] = f2tf(Qr1[ks * 8 + l4 + 4] * qscale);
        }
    }

    float o[16][4];
    #pragma unroll
    for (int nf = 0; nf < 16; nf++)
        #pragma unroll
        for (int r = 0; r < 4; r++) o[nf][r] = 0.f;
    float m0r = -1e30f, m1r = -1e30f;
    float l0r = 0.f,    l1r = 0.f;

    for (int kt = 0; kt < nkt; kt++) {
        // prefetch next tile into the other buffer (reads of it finished at
        // the trailing __syncthreads of the previous iteration)
        if (kt + 1 < nkt) {
            issue_kv((kt + 1) & 1, kt + 1);
            asm volatile("cp.async.commit_group;\n");
            asm volatile("cp.async.wait_group 1;\n");
        } else {
            asm volatile("cp.async.wait_group 0;\n");
        }
        __syncthreads();
        const unsigned* Ks = smu + (kt & 1) * 17152;
        const unsigned* Vs = Ks + 8448;
        const int k0 = kt * 64;

        // ---- S = Q @ K^T ----
        float sc[8][4];
        #pragma unroll
        for (int ni = 0; ni < 8; ni++)
            #pragma unroll
            for (int r = 0; r < 4; r++) sc[ni][r] = 0.f;
        #pragma unroll
        for (int ks = 0; ks < 16; ks++) {
            #pragma unroll
            for (int ni = 0; ni < 8; ni++) {
                unsigned bf[2];
                const unsigned* kp = &Ks[(ni * 8 + l2) * 132 + ks * 8 + l4];
                bf[0] = kp[0];
                bf[1] = kp[4];
                mma_tf32(sc[ni], qf[ks], bf);
            }
        }

        // ---- causal mask ----
        if (kt >= 2 * blk) {
            const int row0 = q0 + wm + l2;
            const int row1 = row0 + 8;
            #pragma unroll
            for (int ni = 0; ni < 8; ni++) {
                const int col = k0 + ni * 8 + 2 * l4;
                if (col     > row0) sc[ni][0] = -1e30f;
                if (col + 1 > row0) sc[ni][1] = -1e30f;
                if (col     > row1) sc[ni][2] = -1e30f;
                if (col + 1 > row1) sc[ni][3] = -1e30f;
            }
        }

        // ---- online softmax in fragment registers ----
        float mx0 = -1e30f, mx1 = -1e30f;
        #pragma unroll
        for (int ni = 0; ni < 8; ni++) {
            mx0 = fmaxf(mx0, fmaxf(sc[ni][0], sc[ni][1]));
            mx1 = fmaxf(mx1, fmaxf(sc[ni][2], sc[ni][3]));
        }
        mx0 = fmaxf(mx0, __shfl_xor_sync(0xffffffffu, mx0, 1));
        mx0 = fmaxf(mx0, __shfl_xor_sync(0xffffffffu, mx0, 2));
        mx1 = fmaxf(mx1, __shfl_xor_sync(0xffffffffu, mx1, 1));
        mx1 = fmaxf(mx1, __shfl_xor_sync(0xffffffffu, mx1, 2));
        const float mn0 = fmaxf(m0r, mx0);
        const float mn1 = fmaxf(m1r, mx1);
        float sum0 = 0.f, sum1 = 0.f;
        #pragma unroll
        for (int ni = 0; ni < 8; ni++) {
            sc[ni][0] = exp2f(sc[ni][0] - mn0);
            sc[ni][1] = exp2f(sc[ni][1] - mn0);
            sc[ni][2] = exp2f(sc[ni][2] - mn1);
            sc[ni][3] = exp2f(sc[ni][3] - mn1);
            sum0 += sc[ni][0] + sc[ni][1];
            sum1 += sc[ni][2] + sc[ni][3];
        }
        sum0 += __shfl_xor_sync(0xffffffffu, sum0, 1);
        sum0 += __shfl_xor_sync(0xffffffffu, sum0, 2);
        sum1 += __shfl_xor_sync(0xffffffffu, sum1, 1);
        sum1 += __shfl_xor_sync(0xffffffffu, sum1, 2);
        const float a0 = exp2f(m0r - mn0);
        const float a1 = exp2f(m1r - mn1);
        m0r = mn0; m1r = mn1;
        l0r = fmaf(a0, l0r, sum0);
        l1r = fmaf(a1, l1r, sum1);

        // ---- stage P (tf32) ----
        {
            unsigned* p0 = &Ps[(wm + l2)     * 72 + 2 * l4];
            unsigned* p1 = &Ps[(wm + l2 + 8) * 72 + 2 * l4];
            #pragma unroll
            for (int ni = 0; ni < 8; ni++) {
                uint2 t0; t0.x = f2tf(sc[ni][0]); t0.y = f2tf(sc[ni][1]);
                *(uint2*)&p0[ni * 8] = t0;
                uint2 t1; t1.x = f2tf(sc[ni][2]); t1.y = f2tf(sc[ni][3]);
                *(uint2*)&p1[ni * 8] = t1;
            }
        }

        #pragma unroll
        for (int nf = 0; nf < 16; nf++) {
            o[nf][0] *= a0; o[nf][1] *= a0;
            o[nf][2] *= a1; o[nf][3] *= a1;
        }
        __syncthreads();

        // ---- O += P @ V ----
        #pragma unroll
        for (int kv = 0; kv < 8; kv++) {
            unsigned af[4];
            const unsigned* pr0 = &Ps[(wm + l2)     * 72 + kv * 8 + l4];
            const unsigned* pr1 = &Ps[(wm + l2 + 8) * 72 + kv * 8 + l4];
            af[0] = pr0[0];
            af[1] = pr1[0];
            af[2] = pr0[4];
            af[3] = pr1[4];
            #pragma unroll
            for (int nf = 0; nf < 16; nf++) {
                unsigned bf[2];
                const unsigned* vp = &Vs[(kv * 8 + l4) * 136 + nf * 8 + l2];
                bf[0] = vp[0];
                bf[1] = vp[4 * 136];
                mma_tf32(o[nf], af, bf);
            }
        }
        __syncthreads();   // all PV reads done before next prefetch overwrites
    }

    // ---- normalize and write (tf32-rounded: feeds gemm<1> A via cp.async) ----
    const float inv0 = 1.0f / l0r;
    const float inv1 = 1.0f / l1r;
    float* O0 = Out + base + (size_t)(q0 + wm + l2) * HH;
    float* O1 = O0 + 8 * HH;
    #pragma unroll
    for (int nf = 0; nf < 16; nf++) {
        *(float2*)&O0[nf * 8 + 2 * l4] = make_float2(roundtf(o[nf][0] * inv0), roundtf(o[nf][1] * inv0));
        *(float2*)&O1[nf * 8 + 2 * l4] = make_float2(roundtf(o[nf][2] * inv1), roundtf(o[nf][3] * inv1));
    }
}

// ---------------- host launcher ----------------
extern "C" void kernel_launch(void* const* d_in, const int* in_sizes, int n_in,
                              void* d_out, int out_size)
{
    const float* x    = (const float*)d_in[0];
    const float* wq   = (const float*)d_in[1];
    const float* wk   = (const float*)d_in[2];
    const float* wv   = (const float*)d_in[3];
    const float* wo   = (const float*)d_in[4];
    const float* ln1s = (const float*)d_in[5];
    const float* ln1b = (const float*)d_in[6];
    const float* ln2s = (const float*)d_in[7];
    const float* ln2b = (const float*)d_in[8];
    const float* w1   = (const float*)d_in[9];
    const float* b1   = (const float*)d_in[10];
    const float* w2   = (const float*)d_in[11];
    const float* b2   = (const float*)d_in[12];
    float* out = (float*)d_out;

    float *h, *q, *k, *v, *attn, *act;
    float *cwq, *cwk, *cwv, *cwo, *cw1, *cw2;
    cudaGetSymbolAddress((void**)&h,    g_h);
    cudaGetSymbolAddress((void**)&q,    g_q);
    cudaGetSymbolAddress((void**)&k,    g_k);
    cudaGetSymbolAddress((void**)&v,    g_v);
    cudaGetSymbolAddress((void**)&attn, g_attn);
    cudaGetSymbolAddress((void**)&act,  g_act);
    cudaGetSymbolAddress((void**)&cwq,  g_wq);
    cudaGetSymbolAddress((void**)&cwk,  g_wk);
    cudaGetSymbolAddress((void**)&cwv,  g_wv);
    cudaGetSymbolAddress((void**)&cwo,  g_wo);
    cudaGetSymbolAddress((void**)&cw1,  g_w1);
    cudaGetSymbolAddress((void**)&cw2,  g_w2);

    const int M = MM, H = HH, F = FF;
    const dim3 gH(H / 128, M / 128);
    const int gsm = (4 * 2560 + 4 * 2176) * 4;     // 75776 B
    cudaFuncSetAttribute(gemm_tc<0>, cudaFuncAttributeMaxDynamicSharedMemorySize, gsm);
    cudaFuncSetAttribute(gemm_tc<1>, cudaFuncAttributeMaxDynamicSharedMemorySize, gsm);
    cudaFuncSetAttribute(gemm_tc<2>, cudaFuncAttributeMaxDynamicSharedMemorySize, gsm);
    cudaFuncSetAttribute(gemm_tc<3>, cudaFuncAttributeMaxDynamicSharedMemorySize, gsm);

    // 0. pre-round weights to tf32
    {
        const int nHH = H * H / 4, nHF = H * F / 4;
        round_tf32_kernel<<<(nHH + 255) / 256, 256>>>((const float4*)wq, (float4*)cwq, nHH);
        round_tf32_kernel<<<(nHH + 255) / 256, 256>>>((const float4*)wk, (float4*)cwk, nHH);
        round_tf32_kernel<<<(nHH + 255) / 256, 256>>>((const float4*)wv, (float4*)cwv, nHH);
        round_tf32_kernel<<<(nHH + 255) / 256, 256>>>((const float4*)wo, (float4*)cwo, nHH);
        round_tf32_kernel<<<(nHF + 255) / 256, 256>>>((const float4*)w1, (float4*)cw1, nHF);
        round_tf32_kernel<<<(nHF + 255) / 256, 256>>>((const float4*)w2, (float4*)cw2, nHF);
    }

    // 1. LN1 (tf32-rounded output)
    ln_kernel<<<M, 256>>>(x, ln1s, ln1b, h);
    // 2-4. QKV projections (outputs tf32-rounded for the attn cp.async path)
    gemm_tc<0><<<gH, 256, gsm>>>(h, cwq, nullptr, nullptr, q, M, H, H);
    gemm_tc<0><<<gH, 256, gsm>>>(h, cwk, nullptr, nullptr, k, M, H, H);
    gemm_tc<0><<<gH, 256, gsm>>>(h, cwv, nullptr, nullptr, v, M, H, H);
    // 5. causal flash attention (2-stage cp.async K/V pipeline)
    const int smsize = (2 * 17152 + 9216) * 4;     // 174080 B
    cudaFuncSetAttribute(attn_tc, cudaFuncAttributeMaxDynamicSharedMemorySize, smsize);
    attn_tc<<<dim3(TT / 128, BB * NHH), 256, smsize>>>(q, k, v, attn);
    // 6. out = x + attn @ wo
    gemm_tc<1><<<gH, 256, gsm>>>(attn, cwo, nullptr, x, out, M, H, H);
    // 7. LN2
    ln_kernel<<<M, 256>>>(out, ln2s, ln2b, h);
    // 8. act = gelu(h @ w1 + b1)
    gemm_tc<2><<<dim3(F / 128, M / 128), 256, gsm>>>(h, cw1, b1, nullptr, act, M, F, H);
    // 9. out += act @ w2 + b2
    gemm_tc<3><<<gH, 256, gsm>>>(act, cw2, b2, nullptr, out, M, H, F);
}

// round 14
// speedup vs baseline: 3.4427x; 1.0232x over previous
#include <cuda_runtime.h>
#include <math.h>

// Problem constants
#define BB 2
#define TT 2048
#define HH 2048
#define NHH 16
#define HDD 128
#define MM (BB*TT)     // 4096 rows
#define FF (4*HH)      // 8192 ffn dim

// ---------------- scratch (static device globals; no allocs) ----------------
__device__ float g_h[(size_t)MM * HH];      // LN output (reused for LN1 and LN2)
__device__ float g_q[(size_t)MM * HH];
__device__ float g_k[(size_t)MM * HH];
__device__ float g_v[(size_t)MM * HH];
__device__ float g_attn[(size_t)MM * HH];
__device__ float g_act[(size_t)MM * FF];    // FFN hidden activations
// tf32-rounded weight copies
__device__ float g_wq[(size_t)HH * HH];
__device__ float g_wk[(size_t)HH * HH];
__device__ float g_wv[(size_t)HH * HH];
__device__ float g_wo[(size_t)HH * HH];
__device__ float g_w1[(size_t)HH * FF];
__device__ float g_w2[(size_t)FF * HH];

__device__ __forceinline__ unsigned f2tf(float x) {
    unsigned u;
    asm("cvt.rna.tf32.f32 %0, %1;" : "=r"(u) : "f"(x));
    return u;
}
__device__ __forceinline__ float roundtf(float x) { return __uint_as_float(f2tf(x)); }

// gelu-tanh via hardware EX2/RCP: tanh(z) = 1 - 2/(1+e^{2z})
// => gelu(x) = x * e^{2z}/(1+e^{2z}), z = 0.79788456(x + 0.044715 x^3).
// Clamp exponent to avoid inf/inf. |err| ~1e-6, far below tf32 noise.
__device__ __forceinline__ float gelu_tanh_f(float x) {
    float z = 0.7978845608028654f * (x + 0.044715f * x * x * x);
    float e = exp2f(fminf(2.8853900817779268f * z, 120.0f));
    return x * __fdividef(e, 1.0f + e);
}

__device__ __forceinline__ void mma_tf32(float d[4], const unsigned a[4], const unsigned b[2]) {
    asm volatile(
        "mma.sync.aligned.m16n8k8.row.col.f32.tf32.tf32.f32 "
        "{%0,%1,%2,%3}, {%4,%5,%6,%7}, {%8,%9}, {%0,%1,%2,%3};\n"
        : "+f"(d[0]), "+f"(d[1]), "+f"(d[2]), "+f"(d[3])
        : "r"(a[0]), "r"(a[1]), "r"(a[2]), "r"(a[3]), "r"(b[0]), "r"(b[1]));
}

__device__ __forceinline__ void cp16(void* smem_dst, const void* gmem_src) {
    unsigned s = (unsigned)__cvta_generic_to_shared(smem_dst);
    asm volatile("cp.async.cg.shared.global [%0], [%1], 16;\n" :: "r"(s), "l"(gmem_src));
}

// ---------------- tf32 pre-rounding of all 6 weight matrices, one launch ----
__global__ void __launch_bounds__(256)
round_all_kernel(const float4* i0, float4* o0, int n0,
                 const float4* i1, float4* o1, int n1,
                 const float4* i2, float4* o2, int n2,
                 const float4* i3, float4* o3, int n3,
                 const float4* i4, float4* o4, int n4,
                 const float4* i5, float4* o5, int n5)
{
    const float4* in; float4* out; int n;
    switch (blockIdx.y) {
        case 0: in = i0; out = o0; n = n0; break;
        case 1: in = i1; out = o1; n = n1; break;
        case 2: in = i2; out = o2; n = n2; break;
        case 3: in = i3; out = o3; n = n3; break;
        case 4: in = i4; out = o4; n = n4; break;
        default: in = i5; out = o5; n = n5; break;
    }
    int i = blockIdx.x * 256 + threadIdx.x;
    if (i < n) {
        float4 v = in[i];
        float4 r;
        r.x = roundtf(v.x); r.y = roundtf(v.y);
        r.z = roundtf(v.z); r.w = roundtf(v.w);
        out[i] = r;
    }
}

// ---------------- LayerNorm: one block per row (tf32-rounded output) --------
__global__ void __launch_bounds__(256)
ln_kernel(const float* __restrict__ x, const float* __restrict__ gam,
          const float* __restrict__ bet, float* __restrict__ y)
{
    const int row = blockIdx.x;
    const int tid = threadIdx.x;
    const float* xr = x + (size_t)row * HH;
    float v[8];
    *(float4*)&v[0] = *(const float4*)(xr + tid * 8);
    *(float4*)&v[4] = *(const float4*)(xr + tid * 8 + 4);
    float s = 0.f, ss = 0.f;
    #pragma unroll
    for (int i = 0; i < 8; i++) { s += v[i]; ss = fmaf(v[i], v[i], ss); }
    #pragma unroll
    for (int off = 16; off > 0; off >>= 1) {
        s  += __shfl_xor_sync(0xffffffffu, s,  off);
        ss += __shfl_xor_sync(0xffffffffu, ss, off);
    }
    __shared__ float rs[8], rss[8], stats[2];
    const int warp = tid >> 5;
    if ((tid & 31) == 0) { rs[warp] = s; rss[warp] = ss; }
    __syncthreads();
    if (tid == 0) {
        float S = 0.f, SS = 0.f;
        #pragma unroll
        for (int w = 0; w < 8; w++) { S += rs[w]; SS += rss[w]; }
        float mean = S * (1.0f / HH);
        float var  = SS * (1.0f / HH) - mean * mean;
        stats[0] = mean;
        stats[1] = rsqrtf(var + 1e-5f);
    }
    __syncthreads();
    const float mean = stats[0], inv = stats[1];
    float g[8], b[8];
    *(float4*)&g[0] = *(const float4*)(gam + tid * 8);
    *(float4*)&g[4] = *(const float4*)(gam + tid * 8 + 4);
    *(float4*)&b[0] = *(const float4*)(bet + tid * 8);
    *(float4*)&b[4] = *(const float4*)(bet + tid * 8 + 4);
    float o[8];
    #pragma unroll
    for (int i = 0; i < 8; i++) o[i] = roundtf(fmaf(g[i], (v[i] - mean) * inv, b[i]));
    float* yp = y + (size_t)row * HH + tid * 8;
    *(float4*)yp       = make_float4(o[0], o[1], o[2], o[3]);
    *(float4*)(yp + 4) = make_float4(o[4], o[5], o[6], o[7]);
}

// ---------------- GEMM core (4-stage cp.async, tf32 mma) --------------------
// Computes a 128x128 tile of A[M,K]@B[K,N] into acc. Caller does the epilogue.
struct GemmFrag { float acc[2][8][4]; };

template<typename Epi>
__device__ __forceinline__ void gemm_core(
    const float* __restrict__ A, const float* __restrict__ B,
    int M, int N, int K, int m0, int n0, Epi epi)
{
    extern __shared__ float smem[];
    float* sA = smem;                 // 4 stages x 128*20
    float* sB = smem + 4 * 2560;      // 4 stages x 16*136

    const int tid  = threadIdx.x;
    const int lane = tid & 31;
    const int warp = tid >> 5;
    const int l4 = lane & 3;
    const int l2 = lane >> 2;
    const int wm = (warp & 3) * 32;
    const int wn = (warp >> 2) * 64;

    const int am  = tid >> 2;
    const int akq = (tid & 3) * 4;
    const int bk  = tid >> 5;
    const int bnq = (tid & 31) * 4;

    float acc[2][8][4];
    #pragma unroll
    for (int mi = 0; mi < 2; mi++)
        #pragma unroll
        for (int ni = 0; ni < 8; ni++)
            #pragma unroll
            for (int r = 0; r < 4; r++) acc[mi][ni][r] = 0.f;

    const int nt = K >> 4;

    auto issue = [&](int stage, int kt) {
        const int k0 = kt << 4;
        float* a_s = sA + stage * 2560;
        float* b_s = sB + stage * 2176;
        cp16(a_s + am * 20 + akq,        A + (size_t)(m0 + am) * K + k0 + akq);
        cp16(a_s + (am + 64) * 20 + akq, A + (size_t)(m0 + am + 64) * K + k0 + akq);
        cp16(b_s + bk * 136 + bnq,       B + (size_t)(k0 + bk) * N + n0 + bnq);
        cp16(b_s + (bk + 8) * 136 + bnq, B + (size_t)(k0 + bk + 8) * N + n0 + bnq);
    };

    #pragma unroll
    for (int s = 0; s < 3; s++) {
        issue(s, s);
        asm volatile("cp.async.commit_group;\n");
    }

    for (int it = 0; it < nt; ++it) {
        asm volatile("cp.async.wait_group 2;\n");
        __syncthreads();
        const int pf = it + 3;
        if (pf < nt) issue(pf & 3, pf);
        asm volatile("cp.async.commit_group;\n");

        const float* As_ = sA + (it & 3) * 2560;
        const float* Bs_ = sB + (it & 3) * 2176;
        #pragma unroll
        for (int kb = 0; kb < 16; kb += 8) {
            unsigned af[2][4];
            #pragma unroll
            for (int mi = 0; mi < 2; mi++) {
                const float* ap = As_ + (wm + mi * 16 + l2) * 20 + kb + l4;
                af[mi][0] = __float_as_uint(ap[0]);
                af[mi][1] = __float_as_uint(ap[160]);
                af[mi][2] = __float_as_uint(ap[4]);
                af[mi][3] = __float_as_uint(ap[164]);
            }
            unsigned bf[8][2];
            #pragma unroll
            for (int ni = 0; ni < 8; ni++) {
                const float* bp = Bs_ + (kb + l4) * 136 + wn + ni * 8 + l2;
                bf[ni][0] = __float_as_uint(bp[0]);
                bf[ni][1] = __float_as_uint(bp[544]);
            }
            #pragma unroll
            for (int mi = 0; mi < 2; mi++)
                #pragma unroll
                for (int ni = 0; ni < 8; ni++)
                    mma_tf32(acc[mi][ni], af[mi], bf[ni]);
        }
    }

    // Epilogue: c-frag layout -> float2 (cols 2*l4, 2*l4+1)
    #pragma unroll
    for (int mi = 0; mi < 2; mi++) {
        #pragma unroll
        for (int h = 0; h < 2; h++) {
            const int row = m0 + wm + mi * 16 + h * 8 + l2;
            #pragma unroll
            for (int ni = 0; ni < 8; ni++) {
                const int col = n0 + wn + ni * 8 + l4 * 2;
                epi(row, col, acc[mi][ni][2 * h], acc[mi][ni][2 * h + 1]);
            }
        }
    }
}

// QKV fused: blockIdx.z selects (wq->q, wk->k, wv->v). EPI: tf32-round.
__global__ void __launch_bounds__(256, 2)
gemm_qkv(const float* __restrict__ A,
         const float* __restrict__ Bq, const float* __restrict__ Bk,
         const float* __restrict__ Bv,
         float* __restrict__ Cq, float* __restrict__ Ck, float* __restrict__ Cv,
         int M, int N, int K)
{
    const float* B = (blockIdx.z == 0) ? Bq : (blockIdx.z == 1) ? Bk : Bv;
    float*       C = (blockIdx.z == 0) ? Cq : (blockIdx.z == 1) ? Ck : Cv;
    gemm_core(A, B, M, N, K, blockIdx.y * 128, blockIdx.x * 128,
        [&](int row, int col, float v0, float v1) {
            *(float2*)(C + (size_t)row * N + col) =
                make_float2(roundtf(v0), roundtf(v1));
        });
}

// EPI 1: C = acc + res
__global__ void __launch_bounds__(256, 2)
gemm_res(const float* __restrict__ A, const float* __restrict__ B,
         const float* __restrict__ res, float* __restrict__ C,
         int M, int N, int K)
{
    gemm_core(A, B, M, N, K, blockIdx.y * 128, blockIdx.x * 128,
        [&](int row, int col, float v0, float v1) {
            const size_t off = (size_t)row * N + col;
            float2 r = *(const float2*)(res + off);
            *(float2*)(C + off) = make_float2(v0 + r.x, v1 + r.y);
        });
}

// EPI 2: C = tf32(gelu(acc + bias[n]))
__global__ void __launch_bounds__(256, 2)
gemm_gelu(const float* __restrict__ A, const float* __restrict__ B,
          const float* __restrict__ bias, float* __restrict__ C,
          int M, int N, int K)
{
    gemm_core(A, B, M, N, K, blockIdx.y * 128, blockIdx.x * 128,
        [&](int row, int col, float v0, float v1) {
            *(float2*)(C + (size_t)row * N + col) = make_float2(
                roundtf(gelu_tanh_f(v0 + bias[col])),
                roundtf(gelu_tanh_f(v1 + bias[col + 1])));
        });
}

// EPI 3: C = acc + bias[n] + C
__global__ void __launch_bounds__(256, 2)
gemm_bias_acc(const float* __restrict__ A, const float* __restrict__ B,
              const float* __restrict__ bias, float* __restrict__ C,
              int M, int N, int K)
{
    gemm_core(A, B, M, N, K, blockIdx.y * 128, blockIdx.x * 128,
        [&](int row, int col, float v0, float v1) {
            const size_t off = (size_t)row * N + col;
            float2 c = *(const float2*)(C + off);
            *(float2*)(C + off) = make_float2(v0 + c.x + bias[col],
                                              v1 + c.y + bias[col + 1]);
        });
}

// ---------------- TF32 flash attention, 2-stage cp.async K/V pipeline -------
// CTA: 128 q-rows x one head; 8 warps, warp w owns rows [16w, 16w+16).
// P staging is warp-private -> only __syncwarp between P store and PV.
// Ps stride 68: PV a-frag loads bank-clean (4*l2+l4 bijective).
// smem: 2 stages x (Ks[64][132] + Vs[64][136]) + Ps[128][68] = 172032 B.
__global__ void __launch_bounds__(256, 1)
attn_tc(const float* __restrict__ Q, const float* __restrict__ K,
        const float* __restrict__ V, float* __restrict__ Out)
{
    extern __shared__ unsigned smu[];
    unsigned* Ps = smu + 34304;    // [128][68]

    const int tid  = threadIdx.x;
    const int lane = tid & 31;
    const int warp = tid >> 5;
    const int l4 = lane & 3;
    const int l2 = lane >> 2;
    const int wm = warp * 16;
    const int blk = gridDim.x - 1 - blockIdx.x;    // heavy diagonal CTAs first
    const int q0 = blk * 128;
    const int b  = blockIdx.y >> 4;
    const int h  = blockIdx.y & 15;
    const size_t base = (size_t)b * TT * HH + (size_t)h * HDD;
    const float qscale = 0.12751744116f;   // log2(e) / sqrt(128)

    const int nkt = 2 * blk + 2;

    auto issue_kv = [&](int stage, int kt) {
        unsigned* Ks = smu + stage * 17152;
        unsigned* Vs = Ks + 8448;
        const int k0 = kt * 64;
        #pragma unroll
        for (int it = 0; it < 8; it++) {
            int chunk = tid + it * 256;
            int key = chunk >> 5;
            int d0  = (chunk & 31) << 2;
            cp16(&Ks[key * 132 + d0], K + base + (size_t)(k0 + key) * HH + d0);
            cp16(&Vs[key * 136 + d0], V + base + (size_t)(k0 + key) * HH + d0);
        }
    };

    issue_kv(0, 0);
    asm volatile("cp.async.commit_group;\n");

    // Q a-frags: 16 k-steps x 4 regs, resident for the whole CTA
    unsigned qf[16][4];
    {
        const float* Qr0 = Q + base + (size_t)(q0 + wm + l2) * HH;
        const float* Qr1 = Qr0 + 8 * HH;
        #pragma unroll
        for (int ks = 0; ks < 16; ks++) {
            qf[ks][0] = f2tf(Qr0[ks * 8 + l4]     * qscale);
            qf[ks][1] = f2tf(Qr1[ks * 8 + l4]     * qscale);
            qf[ks][2] = f2tf(Qr0[ks * 8 + l4 + 4] * qscale);
            qf[ks][3] = f2tf(Qr1[ks * 8 + l4 + 4] * qscale);
        }
    }

    float o[16][4];
    #pragma unroll
    for (int nf = 0; nf < 16; nf++)
        #pragma unroll
        for (int r = 0; r < 4; r++) o[nf][r] = 0.f;
    float m0r = -1e30f, m1r = -1e30f;
    float l0r = 0.f,    l1r = 0.f;

    for (int kt = 0; kt < nkt; kt++) {
        if (kt + 1 < nkt) {
            issue_kv((kt + 1) & 1, kt + 1);
            asm volatile("cp.async.commit_group;\n");
            asm volatile("cp.async.wait_group 1;\n");
        } else {
            asm volatile("cp.async.wait_group 0;\n");
        }
        __syncthreads();
        const unsigned* Ks = smu + (kt & 1) * 17152;
        const unsigned* Vs = Ks + 8448;
        const int k0 = kt * 64;

        // ---- S = Q @ K^T ----
        float sc[8][4];
        #pragma unroll
        for (int ni = 0; ni < 8; ni++)
            #pragma unroll
            for (int r = 0; r < 4; r++) sc[ni][r] = 0.f;
        #pragma unroll
        for (int ks = 0; ks < 16; ks++) {
            #pragma unroll
            for (int ni = 0; ni < 8; ni++) {
                unsigned bf[2];
                const unsigned* kp = &Ks[(ni * 8 + l2) * 132 + ks * 8 + l4];
                bf[0] = kp[0];
                bf[1] = kp[4];
                mma_tf32(sc[ni], qf[ks], bf);
            }
        }

        // ---- causal mask ----
        if (kt >= 2 * blk) {
            const int row0 = q0 + wm + l2;
            const int row1 = row0 + 8;
            #pragma unroll
            for (int ni = 0; ni < 8; ni++) {
                const int col = k0 + ni * 8 + 2 * l4;
                if (col     > row0) sc[ni][0] = -1e30f;
                if (col + 1 > row0) sc[ni][1] = -1e30f;
                if (col     > row1) sc[ni][2] = -1e30f;
                if (col + 1 > row1) sc[ni][3] = -1e30f;
            }
        }

        // ---- online softmax in fragment registers ----
        float mx0 = -1e30f, mx1 = -1e30f;
        #pragma unroll
        for (int ni = 0; ni < 8; ni++) {
            mx0 = fmaxf(mx0, fmaxf(sc[ni][0], sc[ni][1]));
            mx1 = fmaxf(mx1, fmaxf(sc[ni][2], sc[ni][3]));
        }
        mx0 = fmaxf(mx0, __shfl_xor_sync(0xffffffffu, mx0, 1));
        mx0 = fmaxf(mx0, __shfl_xor_sync(0xffffffffu, mx0, 2));
        mx1 = fmaxf(mx1, __shfl_xor_sync(0xffffffffu, mx1, 1));
        mx1 = fmaxf(mx1, __shfl_xor_sync(0xffffffffu, mx1, 2));
        const float mn0 = fmaxf(m0r, mx0);
        const float mn1 = fmaxf(m1r, mx1);
        float sum0 = 0.f, sum1 = 0.f;
        #pragma unroll
        for (int ni = 0; ni < 8; ni++) {
            sc[ni][0] = exp2f(sc[ni][0] - mn0);
            sc[ni][1] = exp2f(sc[ni][1] - mn0);
            sc[ni][2] = exp2f(sc[ni][2] - mn1);
            sc[ni][3] = exp2f(sc[ni][3] - mn1);
            sum0 += sc[ni][0] + sc[ni][1];
            sum1 += sc[ni][2] + sc[ni][3];
        }
        sum0 += __shfl_xor_sync(0xffffffffu, sum0, 1);
        sum0 += __shfl_xor_sync(0xffffffffu, sum0, 2);
        sum1 += __shfl_xor_sync(0xffffffffu, sum1, 1);
        sum1 += __shfl_xor_sync(0xffffffffu, sum1, 2);
        const float a0 = exp2f(m0r - mn0);
        const float a1 = exp2f(m1r - mn1);
        m0r = mn0; m1r = mn1;
        l0r = fmaf(a0, l0r, sum0);
        l1r = fmaf(a1, l1r, sum1);

        // ---- stage P (tf32), warp-private rows ----
        {
            unsigned* p0 = &Ps[(wm + l2)     * 68 + 2 * l4];
            unsigned* p1 = &Ps[(wm + l2 + 8) * 68 + 2 * l4];
            #pragma unroll
            for (int ni = 0; ni < 8; ni++) {
                uint2 t0; t0.x = f2tf(sc[ni][0]); t0.y = f2tf(sc[ni][1]);
                *(uint2*)&p0[ni * 8] = t0;
                uint2 t1; t1.x = f2tf(sc[ni][2]); t1.y = f2tf(sc[ni][3]);
                *(uint2*)&p1[ni * 8] = t1;
            }
        }
        __syncwarp();   // cross-lane STS->LDS visibility; no CTA barrier needed

        #pragma unroll
        for (int nf = 0; nf < 16; nf++) {
            o[nf][0] *= a0; o[nf][1] *= a0;
            o[nf][2] *= a1; o[nf][3] *= a1;
        }

        // ---- O += P @ V ----
        #pragma unroll
        for (int kv = 0; kv < 8; kv++) {
            unsigned af[4];
            const unsigned* pr0 = &Ps[(wm + l2)     * 68 + kv * 8 + l4];
            const unsigned* pr1 = &Ps[(wm + l2 + 8) * 68 + kv * 8 + l4];
            af[0] = pr0[0];
            af[1] = pr1[0];
            af[2] = pr0[4];
            af[3] = pr1[4];
            #pragma unroll
            for (int nf = 0; nf < 16; nf++) {
                unsigned bf[2];
                const unsigned* vp = &Vs[(kv * 8 + l4) * 136 + nf * 8 + l2];
                bf[0] = vp[0];
                bf[1] = vp[4 * 136];
                mma_tf32(o[nf], af, bf);
            }
        }
        __syncthreads();   // all PV reads done before next prefetch overwrites
    }

    // ---- normalize and write (tf32-rounded: feeds gemm_res A via cp.async) ----
    const float inv0 = 1.0f / l0r;
    const float inv1 = 1.0f / l1r;
    float* O0 = Out + base + (size_t)(q0 + wm + l2) * HH;
    float* O1 = O0 + 8 * HH;
    #pragma unroll
    for (int nf = 0; nf < 16; nf++) {
        *(float2*)&O0[nf * 8 + 2 * l4] = make_float2(roundtf(o[nf][0] * inv0), roundtf(o[nf][1] * inv0));
        *(float2*)&O1[nf * 8 + 2 * l4] = make_float2(roundtf(o[nf][2] * inv1), roundtf(o[nf][3] * inv1));
    }
}

// ---------------- host launcher ----------------
extern "C" void kernel_launch(void* const* d_in, const int* in_sizes, int n_in,
                              void* d_out, int out_size)
{
    const float* x    = (const float*)d_in[0];
    const float* wq   = (const float*)d_in[1];
    const float* wk   = (const float*)d_in[2];
    const float* wv   = (const float*)d_in[3];
    const float* wo   = (const float*)d_in[4];
    const float* ln1s = (const float*)d_in[5];
    const float* ln1b = (const float*)d_in[6];
    const float* ln2s = (const float*)d_in[7];
    const float* ln2b = (const float*)d_in[8];
    const float* w1   = (const float*)d_in[9];
    const float* b1   = (const float*)d_in[10];
    const float* w2   = (const float*)d_in[11];
    const float* b2   = (const float*)d_in[12];
    float* out = (float*)d_out;

    float *h, *q, *k, *v, *attn, *act;
    float *cwq, *cwk, *cwv, *cwo, *cw1, *cw2;
    cudaGetSymbolAddress((void**)&h,    g_h);
    cudaGetSymbolAddress((void**)&q,    g_q);
    cudaGetSymbolAddress((void**)&k,    g_k);
    cudaGetSymbolAddress((void**)&v,    g_v);
    cudaGetSymbolAddress((void**)&attn, g_attn);
    cudaGetSymbolAddress((void**)&act,  g_act);
    cudaGetSymbolAddress((void**)&cwq,  g_wq);
    cudaGetSymbolAddress((void**)&cwk,  g_wk);
    cudaGetSymbolAddress((void**)&cwv,  g_wv);
    cudaGetSymbolAddress((void**)&cwo,  g_wo);
    cudaGetSymbolAddress((void**)&cw1,  g_w1);
    cudaGetSymbolAddress((void**)&cw2,  g_w2);

    const int M = MM, H = HH, F = FF;
    const dim3 gH(H / 128, M / 128);
    const int gsm = (4 * 2560 + 4 * 2176) * 4;     // 75776 B
    cudaFuncSetAttribute(gemm_qkv,      cudaFuncAttributeMaxDynamicSharedMemorySize, gsm);
    cudaFuncSetAttribute(gemm_res,      cudaFuncAttributeMaxDynamicSharedMemorySize, gsm);
    cudaFuncSetAttribute(gemm_gelu,     cudaFuncAttributeMaxDynamicSharedMemorySize, gsm);
    cudaFuncSetAttribute(gemm_bias_acc, cudaFuncAttributeMaxDynamicSharedMemorySize, gsm);

    // 0. pre-round all weights to tf32 (single launch)
    {
        const int nHH = H * H / 4, nHF = H * F / 4;
        round_all_kernel<<<dim3((nHF + 255) / 256, 6), 256>>>(
            (const float4*)wq, (float4*)cwq, nHH,
            (const float4*)wk, (float4*)cwk, nHH,
            (const float4*)wv, (float4*)cwv, nHH,
            (const float4*)wo, (float4*)cwo, nHH,
            (const float4*)w1, (float4*)cw1, nHF,
            (const float4*)w2, (float4*)cw2, nHF);
    }

    // 1. LN1 (tf32-rounded output)
    ln_kernel<<<M, 256>>>(x, ln1s, ln1b, h);
    // 2. QKV projections fused into one launch
    gemm_qkv<<<dim3(H / 128, M / 128, 3), 256, gsm>>>(h, cwq, cwk, cwv, q, k, v, M, H, H);
    // 3. causal flash attention
    const int smsize = (2 * 17152 + 8704) * 4;     // 172032 B
    cudaFuncSetAttribute(attn_tc, cudaFuncAttributeMaxDynamicSharedMemorySize, smsize);
    attn_tc<<<dim3(TT / 128, BB * NHH), 256, smsize>>>(q, k, v, attn);
    // 4. out = x + attn @ wo
    gemm_res<<<gH, 256, gsm>>>(attn, cwo, x, out, M, H, H);
    // 5. LN2
    ln_kernel<<<M, 256>>>(out, ln2s, ln2b, h);
    // 6. act = gelu(h @ w1 + b1)
    gemm_gelu<<<dim3(F / 128, M / 128), 256, gsm>>>(h, cw1, b1, act, M, F, H);
    // 7. out += act @ w2 + b2
    gemm_bias_acc<<<gH, 256, gsm>>>(act, cw2, b2, out, M, H, F);
}